// round 14
// baseline (speedup 1.0000x reference)
#include <cuda_runtime.h>
#include <cuda_fp16.h>
#include <cstdint>
#include <math.h>

#define N_NODES 30000
#define E_MAX   480000
#define ET_MAX  (E_MAX + N_NODES)
#define F_IN    1280
#define HEADS   4
#define CH      128
#define HC      512
#define HID     64

// ---------------- scratch ----------------
__device__ __half g_hh[(size_t)N_NODES * HC];    // GAT features (fp16)
__device__ __half g_out1h[(size_t)N_NODES * HC]; // GAT output (fp16)
__device__ __half g_xr[(size_t)N_NODES * HC];    // relu(bn(out1)) fp16
__device__ float g_asrc[N_NODES * HEADS];
__device__ float g_adst[N_NODES * HEADS];
__device__ float g_alpha[(size_t)ET_MAX * HEADS];// fallback only (deg>=128)
__device__ __half g_h2h[(size_t)N_NODES * HID];  // xr @ W_gcn (fp16)
__device__ float g_dinv[N_NODES];
__device__ float g_colsum[HC];
__device__ float g_colsum2[HC];
// CSR
__device__ int   g_cnt[N_NODES];
__device__ int   g_off[N_NODES + 1];
__device__ int   g_esrc[ET_MAX];
__device__ float g_ewc[ET_MAX];
// fp16 operands
__device__ __half g_af[(size_t)N_NODES * F_IN];
__device__ __half g_bf[(size_t)HC * F_IN];       // W_gat^T: [n][k]
__device__ __half g_wgf[(size_t)HID * HC];       // W_gcn^T: [n][k]
// scan partials
#define SCAN_BLOCKS 120
#define SCAN_CHUNK  ((N_NODES + SCAN_BLOCKS - 1) / SCAN_BLOCKS)
__device__ int g_bsum[SCAN_BLOCKS];

// ---------------- init ----------------
__global__ void k_init() {
    int i = blockIdx.x * blockDim.x + threadIdx.x;
    if (i < N_NODES) g_cnt[i] = 0;
    if (i < HC) { g_colsum[i] = 0.0f; g_colsum2[i] = 0.0f; }
}

// ---------------- convert kernels ----------------
__global__ void k_conv_a(const float* __restrict__ X) {
    size_t i = (size_t)blockIdx.x * blockDim.x + threadIdx.x;
    if (i * 4 >= (size_t)N_NODES * F_IN) return;
    float4 v = ((const float4*)X)[i];
    __half2* o = (__half2*)g_af;
    o[i * 2 + 0] = __floats2half2_rn(v.x, v.y);
    o[i * 2 + 1] = __floats2half2_rn(v.z, v.w);
}

__global__ void k_conv_bt(const float* __restrict__ W) {
    int idx = blockIdx.x * blockDim.x + threadIdx.x;
    if (idx >= F_IN * HC) return;
    int k = idx >> 9, n = idx & (HC - 1);
    g_bf[(size_t)n * F_IN + k] = __float2half(W[idx]);
}

__global__ void k_conv_wg(const float* __restrict__ W) {
    int idx = blockIdx.x * blockDim.x + threadIdx.x;
    if (idx >= HC * HID) return;
    int k = idx >> 6, n = idx & (HID - 1);
    g_wgf[(size_t)n * HC + k] = __float2half(W[idx]);
}

// BN-final (inlined) + BN apply + ReLU + fp16 convert. Block = 64 rows.
__global__ void __launch_bounds__(256)
k_conv_xr(const float* __restrict__ gamma, const float* __restrict__ beta) {
    __shared__ float ssc[HC], ssh[HC];
    int t = threadIdx.x;
    for (int c = t; c < HC; c += 256) {
        float mean = g_colsum[c] * (1.0f / N_NODES);
        float var  = g_colsum2[c] * (1.0f / N_NODES) - mean * mean;
        float sc = gamma[c] * rsqrtf(var + 1e-5f);
        ssc[c] = sc;
        ssh[c] = beta[c] - mean * sc;
    }
    __syncthreads();
    int row0 = blockIdx.x * 64;
    for (int idx = t; idx < 64 * 128; idx += 256) {
        int r = row0 + (idx >> 7);
        if (r >= N_NODES) break;
        int cc = (idx & 127) * 4;
        const __half2* ip = (const __half2*)&g_out1h[(size_t)r * HC + cc];
        float2 v01 = __half22float2(ip[0]);
        float2 v23 = __half22float2(ip[1]);
        v01.x = fmaxf(fmaf(v01.x, ssc[cc + 0], ssh[cc + 0]), 0.0f);
        v01.y = fmaxf(fmaf(v01.y, ssc[cc + 1], ssh[cc + 1]), 0.0f);
        v23.x = fmaxf(fmaf(v23.x, ssc[cc + 2], ssh[cc + 2]), 0.0f);
        v23.y = fmaxf(fmaf(v23.y, ssc[cc + 3], ssh[cc + 3]), 0.0f);
        __half2* o = (__half2*)&g_xr[(size_t)r * HC + cc];
        o[0] = __floats2half2_rn(v01.x, v01.y);
        o[1] = __floats2half2_rn(v23.x, v23.y);
    }
}

// ========== shared mma helpers ==========
#define SA 72

__device__ __forceinline__ void mma16816(float* c, const unsigned* a, unsigned b0, unsigned b1) {
    asm volatile(
        "mma.sync.aligned.m16n8k16.row.col.f32.f16.f16.f32 "
        "{%0,%1,%2,%3}, {%4,%5,%6,%7}, {%8,%9}, {%0,%1,%2,%3};\n"
        : "+f"(c[0]), "+f"(c[1]), "+f"(c[2]), "+f"(c[3])
        : "r"(a[0]), "r"(a[1]), "r"(a[2]), "r"(a[3]), "r"(b0), "r"(b1));
}

__device__ __forceinline__ void ldsm4(unsigned* r, const __half* p) {
    unsigned a = (unsigned)__cvta_generic_to_shared(p);
    asm volatile("ldmatrix.sync.aligned.m8n8.x4.shared.b16 {%0,%1,%2,%3}, [%4];\n"
                 : "=r"(r[0]), "=r"(r[1]), "=r"(r[2]), "=r"(r[3]) : "r"(a));
}

__device__ __forceinline__ void cpa16(void* dst, const void* src, int sz) {
    unsigned d = (unsigned)__cvta_generic_to_shared(dst);
    asm volatile("cp.async.cg.shared.global [%0], [%1], 16, %2;\n"
                 :: "r"(d), "l"(src), "r"(sz));
}

// ========== GEMM1: fp16 mma, 128x128 tiles, BK=64, 2 CTAs/SM, fused att dots ==========
#define BM 128
#define BN 128
#define BK 64
#define A_ST   (BM * SA)
#define B_ST   (BN * SA)
#define STAGE_ELEMS (A_ST + B_ST)
#define GEMM1_SMEM (2 * STAGE_ELEMS * 2 + 3072)

__global__ void __launch_bounds__(256, 2)
k_gemm1(const float* __restrict__ att_src, const float* __restrict__ att_dst) {
    extern __shared__ __half sm[];
    float* satt = (float*)(sm + 2 * STAGE_ELEMS);
    float* sred = satt + 256;

    int tid  = threadIdx.x;
    int warp = tid >> 5, lane = tid & 31;
    int head = blockIdx.x;
    int row0 = blockIdx.y * BM, col0 = head * BN;
    int wm = (warp >> 1) * 32, wn = (warp & 1) * 64;

    for (int i = tid; i < CH; i += 256) {
        satt[i]      = att_src[head * CH + i];
        satt[CH + i] = att_dst[head * CH + i];
    }

    float acc[2][8][4];
#pragma unroll
    for (int t = 0; t < 2; t++)
#pragma unroll
        for (int n = 0; n < 8; n++)
#pragma unroll
            for (int j = 0; j < 4; j++) acc[t][n][j] = 0.0f;

    int lrow = tid >> 1, lch0 = (tid & 1) * 4;
    int gra = row0 + lrow;
    int asz = (gra < N_NODES) ? 16 : 0;
    size_t asrc = (size_t)min(gra, N_NODES - 1) * F_IN + lch0 * 8;
    size_t bsrc = (size_t)(col0 + lrow) * F_IN + lch0 * 8;
    int sOff = lrow * SA + lch0 * 8;

    const int NIT = F_IN / BK;

    __half* st[2];
    st[0] = sm;
    st[1] = sm + STAGE_ELEMS;

    int aRow = lane & 15;
    int aK   = (lane >> 4) << 3;
    int bRow = ((lane >> 4) << 3) + (lane & 7);
    int bK   = ((lane >> 3) & 1) << 3;

    {
        __half* s = st[0];
#pragma unroll
        for (int c = 0; c < 4; c++) {
            cpa16(s + sOff + c * 8,        g_af + asrc + c * 8, asz);
            cpa16(s + A_ST + sOff + c * 8, g_bf + bsrc + c * 8, 16);
        }
        asm volatile("cp.async.commit_group;\n");
    }

    for (int it = 0; it < NIT; it++) {
        if (it + 1 < NIT) {
            int k0 = (it + 1) * BK;
            __half* s = st[(it + 1) & 1];
#pragma unroll
            for (int c = 0; c < 4; c++) {
                cpa16(s + sOff + c * 8,        g_af + asrc + k0 + c * 8, asz);
                cpa16(s + A_ST + sOff + c * 8, g_bf + bsrc + k0 + c * 8, 16);
            }
        }
        asm volatile("cp.async.commit_group;\n");
        asm volatile("cp.async.wait_group 1;\n");
        __syncthreads();

        const __half* pA = st[it & 1];
        const __half* pB = pA + A_ST;

#pragma unroll
        for (int kk = 0; kk < BK; kk += 16) {
            unsigned af[2][4];
            ldsm4(af[0], pA + (wm +  0 + aRow) * SA + kk + aK);
            ldsm4(af[1], pA + (wm + 16 + aRow) * SA + kk + aK);
#pragma unroll
            for (int p = 0; p < 4; p++) {
                unsigned bf[4];
                ldsm4(bf, pB + (wn + p * 16 + bRow) * SA + kk + bK);
                int n0 = 2 * p, n1 = 2 * p + 1;
                mma16816(acc[0][n0], af[0], bf[0], bf[1]);
                mma16816(acc[1][n0], af[1], bf[0], bf[1]);
                mma16816(acc[0][n1], af[0], bf[2], bf[3]);
                mma16816(acc[1][n1], af[1], bf[2], bf[3]);
            }
        }
        __syncthreads();
    }

    // ---- epilogue 1: store h (fp16) ----
    int g = lane >> 2, tig = lane & 3;
#pragma unroll
    for (int t = 0; t < 2; t++) {
        int r0 = row0 + wm + t * 16 + g;
#pragma unroll
        for (int n = 0; n < 8; n++) {
            int cc = col0 + wn + n * 8 + tig * 2;
            if (r0 < N_NODES)
                *(__half2*)&g_hh[(size_t)r0 * HC + cc] = __floats2half2_rn(acc[t][n][0], acc[t][n][1]);
            if (r0 + 8 < N_NODES)
                *(__half2*)&g_hh[(size_t)(r0 + 8) * HC + cc] = __floats2half2_rn(acc[t][n][2], acc[t][n][3]);
        }
    }

    // ---- epilogue 2: fused attention dots ----
    float ps[4] = {0.f, 0.f, 0.f, 0.f};
    float pd[4] = {0.f, 0.f, 0.f, 0.f};
#pragma unroll
    for (int t = 0; t < 2; t++) {
#pragma unroll
        for (int n = 0; n < 8; n++) {
            int cc = wn + n * 8 + tig * 2;
            float a0s = satt[cc],      a1s = satt[cc + 1];
            float a0d = satt[CH + cc], a1d = satt[CH + cc + 1];
            ps[t * 2 + 0] += acc[t][n][0] * a0s + acc[t][n][1] * a1s;
            pd[t * 2 + 0] += acc[t][n][0] * a0d + acc[t][n][1] * a1d;
            ps[t * 2 + 1] += acc[t][n][2] * a0s + acc[t][n][3] * a1s;
            pd[t * 2 + 1] += acc[t][n][2] * a0d + acc[t][n][3] * a1d;
        }
    }
#pragma unroll
    for (int o = 1; o <= 2; o <<= 1) {
#pragma unroll
        for (int rc = 0; rc < 4; rc++) {
            ps[rc] += __shfl_xor_sync(0xFFFFFFFFu, ps[rc], o);
            pd[rc] += __shfl_xor_sync(0xFFFFFFFFu, pd[rc], o);
        }
    }
    __syncthreads();
    if (tig == 0) {
#pragma unroll
        for (int rc = 0; rc < 4; rc++) {
            int e = ((warp * 8 + g) * 4 + rc) * 2;
            sred[e + 0] = ps[rc];
            sred[e + 1] = pd[rc];
        }
    }
    __syncthreads();
    if (tid < 128) {
        int wpair = tid >> 5, gg = (tid >> 2) & 7, rc = tid & 3;
        int w0 = wpair * 2, w1 = w0 + 1;
        int e0 = ((w0 * 8 + gg) * 4 + rc) * 2;
        int e1 = ((w1 * 8 + gg) * 4 + rc) * 2;
        int row = row0 + wpair * 32 + rc * 8 + gg;
        if (row < N_NODES) {
            g_asrc[row * 4 + head] = sred[e0 + 0] + sred[e1 + 0];
            g_adst[row * 4 + head] = sred[e0 + 1] + sred[e1 + 1];
        }
    }
}

// ========== GEMM2: fp16 mma, 128x64 tiles, BK=64, 2 CTAs/SM ==========
#define B2_ST  (64 * SA)
#define STAGE2 (A_ST + B2_ST)
#define GEMM2_SMEM (2 * STAGE2 * 2)

__global__ void __launch_bounds__(256, 2)
k_gemm2() {
    extern __shared__ __half sm[];

    int tid  = threadIdx.x;
    int warp = tid >> 5, lane = tid & 31;
    int row0 = blockIdx.x * BM;
    int wm = (warp >> 1) * 32, wn = (warp & 1) * 32;

    float acc[2][4][4];
#pragma unroll
    for (int t = 0; t < 2; t++)
#pragma unroll
        for (int n = 0; n < 4; n++)
#pragma unroll
            for (int j = 0; j < 4; j++) acc[t][n][j] = 0.0f;

    int lrow = tid >> 1, lch0 = (tid & 1) * 4;
    int gra = row0 + lrow;
    int asz = (gra < N_NODES) ? 16 : 0;
    size_t asrc = (size_t)min(gra, N_NODES - 1) * HC + lch0 * 8;
    int sOffA = lrow * SA + lch0 * 8;
    int brow = tid >> 2, bch0 = (tid & 3) * 2;
    size_t bsrc = (size_t)brow * HC + bch0 * 8;
    int sOffB = brow * SA + bch0 * 8;

    const int NIT = HC / BK;

    __half* st[2];
    st[0] = sm;
    st[1] = sm + STAGE2;

    int aRow = lane & 15;
    int aK   = (lane >> 4) << 3;
    int bRow = ((lane >> 4) << 3) + (lane & 7);
    int bK   = ((lane >> 3) & 1) << 3;

    {
        __half* s = st[0];
#pragma unroll
        for (int c = 0; c < 4; c++)
            cpa16(s + sOffA + c * 8, g_xr + asrc + c * 8, asz);
#pragma unroll
        for (int c = 0; c < 2; c++)
            cpa16(s + A_ST + sOffB + c * 8, g_wgf + bsrc + c * 8, 16);
        asm volatile("cp.async.commit_group;\n");
    }

    for (int it = 0; it < NIT; it++) {
        if (it + 1 < NIT) {
            int k0 = (it + 1) * BK;
            __half* s = st[(it + 1) & 1];
#pragma unroll
            for (int c = 0; c < 4; c++)
                cpa16(s + sOffA + c * 8, g_xr + asrc + k0 + c * 8, asz);
#pragma unroll
            for (int c = 0; c < 2; c++)
                cpa16(s + A_ST + sOffB + c * 8, g_wgf + bsrc + k0 + c * 8, 16);
        }
        asm volatile("cp.async.commit_group;\n");
        asm volatile("cp.async.wait_group 1;\n");
        __syncthreads();

        const __half* pA = st[it & 1];
        const __half* pB = pA + A_ST;

#pragma unroll
        for (int kk = 0; kk < BK; kk += 16) {
            unsigned af[2][4];
            ldsm4(af[0], pA + (wm +  0 + aRow) * SA + kk + aK);
            ldsm4(af[1], pA + (wm + 16 + aRow) * SA + kk + aK);
#pragma unroll
            for (int p = 0; p < 2; p++) {
                unsigned bf[4];
                ldsm4(bf, pB + (wn + p * 16 + bRow) * SA + kk + bK);
                int n0 = 2 * p, n1 = 2 * p + 1;
                mma16816(acc[0][n0], af[0], bf[0], bf[1]);
                mma16816(acc[1][n0], af[1], bf[0], bf[1]);
                mma16816(acc[0][n1], af[0], bf[2], bf[3]);
                mma16816(acc[1][n1], af[1], bf[2], bf[3]);
            }
        }
        __syncthreads();
    }

    int g = lane >> 2, tig = lane & 3;
#pragma unroll
    for (int t = 0; t < 2; t++) {
        int r0 = row0 + wm + t * 16 + g;
#pragma unroll
        for (int n = 0; n < 4; n++) {
            int cc = wn + n * 8 + tig * 2;
            if (r0 < N_NODES)
                *(__half2*)&g_h2h[(size_t)r0 * HID + cc] = __floats2half2_rn(acc[t][n][0], acc[t][n][1]);
            if (r0 + 8 < N_NODES)
                *(__half2*)&g_h2h[(size_t)(r0 + 8) * HID + cc] = __floats2half2_rn(acc[t][n][2], acc[t][n][3]);
        }
    }
}

// ---------------- CSR build ----------------
__global__ void k_count(const int* __restrict__ ei, int E) {
    int e = blockIdx.x * blockDim.x + threadIdx.x;
    int ET = E + N_NODES;
    if (e >= ET) return;
    int d = (e < E) ? ei[E + e] : (e - E);
    atomicAdd(&g_cnt[d], 1);
}

__global__ void k_scan1() {
    __shared__ int red[8];
    int b = blockIdx.x, t = threadIdx.x;
    int lo = b * SCAN_CHUNK, hi = min(lo + SCAN_CHUNK, N_NODES);
    int s = 0;
    for (int i = lo + t; i < hi; i += 256) s += g_cnt[i];
#pragma unroll
    for (int o = 16; o > 0; o >>= 1) s += __shfl_xor_sync(0xFFFFFFFFu, s, o);
    if ((t & 31) == 0) red[t >> 5] = s;
    __syncthreads();
    if (t == 0) {
        int tot = 0;
#pragma unroll
        for (int i = 0; i < 8; i++) tot += red[i];
        g_bsum[b] = tot;
    }
}

__global__ void k_scan2() {
    __shared__ int sh[128];
    int t = threadIdx.x;
    int v = (t < SCAN_BLOCKS) ? g_bsum[t] : 0;
    sh[t] = v;
    __syncthreads();
#pragma unroll
    for (int o = 1; o < 128; o <<= 1) {
        int x = (t >= o) ? sh[t - o] : 0;
        __syncthreads();
        sh[t] += x;
        __syncthreads();
    }
    if (t < SCAN_BLOCKS) g_bsum[t] = sh[t] - v;
    if (t == 127) g_off[N_NODES] = sh[127];
}

__global__ void k_scan3() {
    __shared__ int sh[256];
    int b = blockIdx.x, t = threadIdx.x;
    int lo = b * SCAN_CHUNK;
    int i = lo + t;
    int v = (t < SCAN_CHUNK && i < N_NODES) ? g_cnt[i] : 0;
    sh[t] = v;
    __syncthreads();
#pragma unroll
    for (int o = 1; o < 256; o <<= 1) {
        int x = (t >= o) ? sh[t - o] : 0;
        __syncthreads();
        sh[t] += x;
        __syncthreads();
    }
    if (t < SCAN_CHUNK && i < N_NODES) {
        g_off[i] = g_bsum[b] + sh[t] - v;
        g_cnt[i] = 0;
    }
}

__global__ void k_fill(const int* __restrict__ ei, const float* __restrict__ ew, int E) {
    int e = blockIdx.x * blockDim.x + threadIdx.x;
    int ET = E + N_NODES;
    if (e >= ET) return;
    int s, d; float w;
    if (e < E) { s = ei[e]; d = ei[E + e]; w = ew[e]; }
    else       { s = d = e - E; w = 1.0f; }
    int slot = g_off[d] + atomicAdd(&g_cnt[d], 1);
    g_esrc[slot] = s;
    g_ewc[slot]  = w;
}

// ---------------- fused softmax + aggregation (block per node) ----------------
__global__ void __launch_bounds__(128)
k_softagg(const float* __restrict__ b_gat) {
    __shared__ float smax[4][4];
    __shared__ float ssum[4][4];
    __shared__ float sdeg[4];
    __shared__ float salpha[128][4];

    int d = blockIdx.x;
    int tid = threadIdx.x;
    int warp = tid >> 5, lane = tid & 31;
    int beg = g_off[d], end = g_off[d + 1];
    int cnt = end - beg;
    float4 ad = *(const float4*)&g_adst[d * 4];

    if (cnt <= 128) {
        // ---- softmax phase: one edge per thread, logits in registers ----
        int i = beg + tid;
        bool act = tid < cnt;
        float l0 = -1e30f, l1 = -1e30f, l2 = -1e30f, l3 = -1e30f;
        float degw = 0.0f;
        if (act) {
            int s = g_esrc[i];
            float4 as = *(const float4*)&g_asrc[s * 4];
            l0 = as.x + ad.x; l1 = as.y + ad.y; l2 = as.z + ad.z; l3 = as.w + ad.w;
            l0 = l0 > 0.f ? l0 : 0.2f * l0;
            l1 = l1 > 0.f ? l1 : 0.2f * l1;
            l2 = l2 > 0.f ? l2 : 0.2f * l2;
            l3 = l3 > 0.f ? l3 : 0.2f * l3;
            degw = g_ewc[i];
        }
        float m0 = l0, m1 = l1, m2 = l2, m3 = l3, dg = degw;
#pragma unroll
        for (int o = 16; o > 0; o >>= 1) {
            m0 = fmaxf(m0, __shfl_xor_sync(0xFFFFFFFFu, m0, o));
            m1 = fmaxf(m1, __shfl_xor_sync(0xFFFFFFFFu, m1, o));
            m2 = fmaxf(m2, __shfl_xor_sync(0xFFFFFFFFu, m2, o));
            m3 = fmaxf(m3, __shfl_xor_sync(0xFFFFFFFFu, m3, o));
            dg += __shfl_xor_sync(0xFFFFFFFFu, dg, o);
        }
        if (lane == 0) {
            smax[warp][0] = m0; smax[warp][1] = m1;
            smax[warp][2] = m2; smax[warp][3] = m3;
            sdeg[warp] = dg;
        }
        __syncthreads();
        m0 = fmaxf(fmaxf(smax[0][0], smax[1][0]), fmaxf(smax[2][0], smax[3][0]));
        m1 = fmaxf(fmaxf(smax[0][1], smax[1][1]), fmaxf(smax[2][1], smax[3][1]));
        m2 = fmaxf(fmaxf(smax[0][2], smax[1][2]), fmaxf(smax[2][2], smax[3][2]));
        m3 = fmaxf(fmaxf(smax[0][3], smax[1][3]), fmaxf(smax[2][3], smax[3][3]));
        float e0 = act ? __expf(l0 - m0) : 0.f;
        float e1 = act ? __expf(l1 - m1) : 0.f;
        float e2 = act ? __expf(l2 - m2) : 0.f;
        float e3 = act ? __expf(l3 - m3) : 0.f;
        float s0 = e0, s1 = e1, s2 = e2, s3 = e3;
#pragma unroll
        for (int o = 16; o > 0; o >>= 1) {
            s0 += __shfl_xor_sync(0xFFFFFFFFu, s0, o);
            s1 += __shfl_xor_sync(0xFFFFFFFFu, s1, o);
            s2 += __shfl_xor_sync(0xFFFFFFFFu, s2, o);
            s3 += __shfl_xor_sync(0xFFFFFFFFu, s3, o);
        }
        if (lane == 0) {
            ssum[warp][0] = s0; ssum[warp][1] = s1;
            ssum[warp][2] = s2; ssum[warp][3] = s3;
        }
        __syncthreads();
        s0 = ssum[0][0] + ssum[1][0] + ssum[2][0] + ssum[3][0];
        s1 = ssum[0][1] + ssum[1][1] + ssum[2][1] + ssum[3][1];
        s2 = ssum[0][2] + ssum[1][2] + ssum[2][2] + ssum[3][2];
        s3 = ssum[0][3] + ssum[1][3] + ssum[2][3] + ssum[3][3];
        if (act) {
            salpha[tid][0] = e0 / (s0 + 1e-16f);
            salpha[tid][1] = e1 / (s1 + 1e-16f);
            salpha[tid][2] = e2 / (s2 + 1e-16f);
            salpha[tid][3] = e3 / (s3 + 1e-16f);
        }
        if (tid == 0) {
            float dw = sdeg[0] + sdeg[1] + sdeg[2] + sdeg[3];
            g_dinv[d] = dw > 0.f ? rsqrtf(dw) : 0.0f;
        }
        __syncthreads();

        // ---- aggregation phase ----
        int head = tid >> 5;
        int c = tid * 4;
        float4 acc = *(const float4*)&b_gat[c];
        int j = 0;
        for (; j + 1 < cnt; j += 2) {
            int sA = g_esrc[beg + j], sB = g_esrc[beg + j + 1];
            float aA = salpha[j][head], aB = salpha[j + 1][head];
            const __half2* pA = (const __half2*)&g_hh[(size_t)sA * HC + c];
            const __half2* pB = (const __half2*)&g_hh[(size_t)sB * HC + c];
            float2 vA0 = __half22float2(pA[0]), vA1 = __half22float2(pA[1]);
            float2 vB0 = __half22float2(pB[0]), vB1 = __half22float2(pB[1]);
            acc.x = fmaf(vA0.x, aA, acc.x); acc.y = fmaf(vA0.y, aA, acc.y);
            acc.z = fmaf(vA1.x, aA, acc.z); acc.w = fmaf(vA1.y, aA, acc.w);
            acc.x = fmaf(vB0.x, aB, acc.x); acc.y = fmaf(vB0.y, aB, acc.y);
            acc.z = fmaf(vB1.x, aB, acc.z); acc.w = fmaf(vB1.y, aB, acc.w);
        }
        if (j < cnt) {
            int sA = g_esrc[beg + j];
            float aA = salpha[j][head];
            const __half2* pA = (const __half2*)&g_hh[(size_t)sA * HC + c];
            float2 vA0 = __half22float2(pA[0]), vA1 = __half22float2(pA[1]);
            acc.x = fmaf(vA0.x, aA, acc.x); acc.y = fmaf(vA0.y, aA, acc.y);
            acc.z = fmaf(vA1.x, aA, acc.z); acc.w = fmaf(vA1.y, aA, acc.w);
        }
        __half2* o = (__half2*)&g_out1h[(size_t)d * HC + c];
        o[0] = __floats2half2_rn(acc.x, acc.y);
        o[1] = __floats2half2_rn(acc.z, acc.w);
    } else {
        // ---- fallback: strided softmax via g_alpha (deg >= 128) ----
        float m0 = -1e30f, m1 = -1e30f, m2 = -1e30f, m3 = -1e30f, degw = 0.f;
        for (int i = beg + tid; i < end; i += 128) {
            int s = g_esrc[i];
            float4 as = *(const float4*)&g_asrc[s * 4];
            float l0 = as.x + ad.x, l1 = as.y + ad.y, l2 = as.z + ad.z, l3 = as.w + ad.w;
            l0 = l0 > 0.f ? l0 : 0.2f * l0;
            l1 = l1 > 0.f ? l1 : 0.2f * l1;
            l2 = l2 > 0.f ? l2 : 0.2f * l2;
            l3 = l3 > 0.f ? l3 : 0.2f * l3;
            *(float4*)&g_alpha[(size_t)i * 4] = make_float4(l0, l1, l2, l3);
            m0 = fmaxf(m0, l0); m1 = fmaxf(m1, l1);
            m2 = fmaxf(m2, l2); m3 = fmaxf(m3, l3);
            degw += g_ewc[i];
        }
#pragma unroll
        for (int o = 16; o > 0; o >>= 1) {
            m0 = fmaxf(m0, __shfl_xor_sync(0xFFFFFFFFu, m0, o));
            m1 = fmaxf(m1, __shfl_xor_sync(0xFFFFFFFFu, m1, o));
            m2 = fmaxf(m2, __shfl_xor_sync(0xFFFFFFFFu, m2, o));
            m3 = fmaxf(m3, __shfl_xor_sync(0xFFFFFFFFu, m3, o));
            degw += __shfl_xor_sync(0xFFFFFFFFu, degw, o);
        }
        if (lane == 0) {
            smax[warp][0] = m0; smax[warp][1] = m1;
            smax[warp][2] = m2; smax[warp][3] = m3;
            sdeg[warp] = degw;
        }
        __syncthreads();
        m0 = fmaxf(fmaxf(smax[0][0], smax[1][0]), fmaxf(smax[2][0], smax[3][0]));
        m1 = fmaxf(fmaxf(smax[0][1], smax[1][1]), fmaxf(smax[2][1], smax[3][1]));
        m2 = fmaxf(fmaxf(smax[0][2], smax[1][2]), fmaxf(smax[2][2], smax[3][2]));
        m3 = fmaxf(fmaxf(smax[0][3], smax[1][3]), fmaxf(smax[2][3], smax[3][3]));
        float s0 = 0.f, s1 = 0.f, s2 = 0.f, s3 = 0.f;
        for (int i = beg + tid; i < end; i += 128) {
            float4 l = *(const float4*)&g_alpha[(size_t)i * 4];
            float e0 = __expf(l.x - m0), e1 = __expf(l.y - m1);
            float e2 = __expf(l.z - m2), e3 = __expf(l.w - m3);
            *(float4*)&g_alpha[(size_t)i * 4] = make_float4(e0, e1, e2, e3);
            s0 += e0; s1 += e1; s2 += e2; s3 += e3;
        }
#pragma unroll
        for (int o = 16; o > 0; o >>= 1) {
            s0 += __shfl_xor_sync(0xFFFFFFFFu, s0, o);
            s1 += __shfl_xor_sync(0xFFFFFFFFu, s1, o);
            s2 += __shfl_xor_sync(0xFFFFFFFFu, s2, o);
            s3 += __shfl_xor_sync(0xFFFFFFFFu, s3, o);
        }
        if (lane == 0) {
            ssum[warp][0] = s0; ssum[warp][1] = s1;
            ssum[warp][2] = s2; ssum[warp][3] = s3;
        }
        __syncthreads();
        s0 = ssum[0][0] + ssum[1][0] + ssum[2][0] + ssum[3][0];
        s1 = ssum[0][1] + ssum[1][1] + ssum[2][1] + ssum[3][1];
        s2 = ssum[0][2] + ssum[1][2] + ssum[2][2] + ssum[3][2];
        s3 = ssum[0][3] + ssum[1][3] + ssum[2][3] + ssum[3][3];
        float r0 = 1.f / (s0 + 1e-16f), r1 = 1.f / (s1 + 1e-16f);
        float r2 = 1.f / (s2 + 1e-16f), r3 = 1.f / (s3 + 1e-16f);
        for (int i = beg + tid; i < end; i += 128) {
            float4 l = *(const float4*)&g_alpha[(size_t)i * 4];
            *(float4*)&g_alpha[(size_t)i * 4] = make_float4(l.x * r0, l.y * r1, l.z * r2, l.w * r3);
        }
        if (tid == 0) {
            float dw = sdeg[0] + sdeg[1] + sdeg[2] + sdeg[3];
            g_dinv[d] = dw > 0.f ? rsqrtf(dw) : 0.0f;
        }
        __syncthreads();

        int head = tid >> 5;
        int c = tid * 4;
        float4 acc = *(const float4*)&b_gat[c];
        for (int i = beg; i < end; i++) {
            int s = g_esrc[i];
            float a = g_alpha[(size_t)i * 4 + head];
            const __half2* p = (const __half2*)&g_hh[(size_t)s * HC + c];
            float2 v0 = __half22float2(p[0]), v1 = __half22float2(p[1]);
            acc.x = fmaf(v0.x, a, acc.x); acc.y = fmaf(v0.y, a, acc.y);
            acc.z = fmaf(v1.x, a, acc.z); acc.w = fmaf(v1.y, a, acc.w);
        }
        __half2* o = (__half2*)&g_out1h[(size_t)d * HC + c];
        o[0] = __floats2half2_rn(acc.x, acc.y);
        o[1] = __floats2half2_rn(acc.z, acc.w);
    }
}

// ---------------- BN stats (fp16 in, fp32 accum) ----------------
__global__ void k_bnstats() {
    int col = threadIdx.x;
    float s = 0.f, s2 = 0.f;
    for (int r = blockIdx.x; r < N_NODES; r += gridDim.x) {
        float v = __half2float(g_out1h[(size_t)r * HC + col]);
        s += v; s2 += v * v;
    }
    atomicAdd(&g_colsum[col], s);
    atomicAdd(&g_colsum2[col], s2);
}

// ---------------- GCN gather (fp16 h2) ----------------
__global__ void k_gcn(const float* __restrict__ b_gcn, float* __restrict__ out) {
    int d    = (blockIdx.x * blockDim.x + threadIdx.x) >> 5;
    int lane = threadIdx.x & 31;
    if (d >= N_NODES) return;
    float dinv_d = g_dinv[d];
    float2 acc = *(const float2*)&b_gcn[lane * 2];
    int beg = g_off[d], end = g_off[d + 1];
    int i = beg;
    for (; i + 1 < end; i += 2) {
        int s0 = g_esrc[i], s1 = g_esrc[i + 1];
        float n0 = g_dinv[s0] * g_ewc[i] * dinv_d;
        float n1 = g_dinv[s1] * g_ewc[i + 1] * dinv_d;
        float2 v0 = __half22float2(*(const __half2*)&g_h2h[(size_t)s0 * HID + lane * 2]);
        float2 v1 = __half22float2(*(const __half2*)&g_h2h[(size_t)s1 * HID + lane * 2]);
        acc.x = fmaf(v0.x, n0, acc.x); acc.y = fmaf(v0.y, n0, acc.y);
        acc.x = fmaf(v1.x, n1, acc.x); acc.y = fmaf(v1.y, n1, acc.y);
    }
    if (i < end) {
        int s0 = g_esrc[i];
        float n0 = g_dinv[s0] * g_ewc[i] * dinv_d;
        float2 v0 = __half22float2(*(const __half2*)&g_h2h[(size_t)s0 * HID + lane * 2]);
        acc.x = fmaf(v0.x, n0, acc.x); acc.y = fmaf(v0.y, n0, acc.y);
    }
    *(float2*)&out[(size_t)d * HID + lane * 2] = acc;
}

// ---------------- launch ----------------
extern "C" void kernel_launch(void* const* d_in, const int* in_sizes, int n_in,
                              void* d_out, int out_size) {
    const float* x       = (const float*)d_in[0];
    const int*   ei      = (const int*)  d_in[1];
    const float* ew      = (const float*)d_in[2];
    const float* W_gat   = (const float*)d_in[3];
    const float* att_src = (const float*)d_in[4];
    const float* att_dst = (const float*)d_in[5];
    const float* b_gat   = (const float*)d_in[6];
    const float* gamma   = (const float*)d_in[7];
    const float* beta    = (const float*)d_in[8];
    const float* W_gcn   = (const float*)d_in[9];
    const float* b_gcn   = (const float*)d_in[10];
    float* out = (float*)d_out;

    int E  = in_sizes[1] / 2;
    int ET = E + N_NODES;

    static cudaStream_t s_side = nullptr;
    static cudaEvent_t ev_fork = nullptr, ev_join = nullptr;
    if (!s_side) {
        cudaFuncSetAttribute(k_gemm1, cudaFuncAttributeMaxDynamicSharedMemorySize, GEMM1_SMEM);
        cudaFuncSetAttribute(k_gemm2, cudaFuncAttributeMaxDynamicSharedMemorySize, GEMM2_SMEM);
        cudaStreamCreateWithFlags(&s_side, cudaStreamNonBlocking);
        cudaEventCreateWithFlags(&ev_fork, cudaEventDisableTiming);
        cudaEventCreateWithFlags(&ev_join, cudaEventDisableTiming);
    }

    // ---- fork: init + CSR build + W_gcn convert on side stream ----
    cudaEventRecord(ev_fork, 0);
    cudaStreamWaitEvent(s_side, ev_fork, 0);
    k_init<<<(N_NODES + 255) / 256, 256, 0, s_side>>>();
    k_count<<<(ET + 255) / 256, 256, 0, s_side>>>(ei, E);
    k_scan1<<<SCAN_BLOCKS, 256, 0, s_side>>>();
    k_scan2<<<1, 128, 0, s_side>>>();
    k_scan3<<<SCAN_BLOCKS, 256, 0, s_side>>>();
    k_fill<<<(ET + 255) / 256, 256, 0, s_side>>>(ei, ew, E);
    k_conv_wg<<<(HC * HID + 255) / 256, 256, 0, s_side>>>(W_gcn);
    cudaEventRecord(ev_join, s_side);

    // ---- main stream ----
    k_conv_a<<<((N_NODES * (F_IN / 4)) + 255) / 256, 256>>>(x);
    k_conv_bt<<<(F_IN * HC + 255) / 256, 256>>>(W_gat);

    dim3 g1(HC / BN, (N_NODES + BM - 1) / BM);   // (4, 235)
    k_gemm1<<<g1, 256, GEMM1_SMEM>>>(att_src, att_dst);

    cudaStreamWaitEvent(0, ev_join, 0);
    k_softagg<<<N_NODES, 128>>>(b_gat);

    k_bnstats<<<240, 512>>>();
    k_conv_xr<<<(N_NODES + 63) / 64, 256>>>(gamma, beta);

    k_gemm2<<<(N_NODES + BM - 1) / BM, 256, GEMM2_SMEM>>>();
    k_gcn<<<(N_NODES * 32 + 255) / 256, 256>>>(b_gcn, out);
}

// round 15
// speedup vs baseline: 1.0385x; 1.0385x over previous
#include <cuda_runtime.h>
#include <cuda_fp16.h>
#include <cstdint>
#include <math.h>

#define N_NODES 30000
#define E_MAX   480000
#define ET_MAX  (E_MAX + N_NODES)
#define F_IN    1280
#define HEADS   4
#define CH      128
#define HC      512
#define HID     64

// ---------------- scratch ----------------
__device__ __half g_hh[(size_t)N_NODES * HC];    // GAT features (fp16)
__device__ __half g_out1h[(size_t)N_NODES * HC]; // GAT output (fp16)
__device__ __half g_xr[(size_t)N_NODES * HC];    // relu(bn(out1)) fp16
__device__ float g_asrc[N_NODES * HEADS];
__device__ float g_adst[N_NODES * HEADS];
__device__ float g_alpha[(size_t)ET_MAX * HEADS];
__device__ __half g_h2h[(size_t)N_NODES * HID];  // xr @ W_gcn (fp16)
__device__ float g_dinv[N_NODES];
__device__ float g_colsum[HC];
__device__ float g_colsum2[HC];
// CSR
__device__ int   g_cnt[N_NODES];
__device__ int   g_off[N_NODES + 1];
__device__ int   g_esrc[ET_MAX];
__device__ float g_ewc[ET_MAX];
// fp16 operands
__device__ __half g_af[(size_t)N_NODES * F_IN];
__device__ __half g_bf[(size_t)HC * F_IN];       // W_gat^T: [n][k]
__device__ __half g_wgf[(size_t)HID * HC];       // W_gcn^T: [n][k]
// scan partials
#define SCAN_BLOCKS 120
#define SCAN_CHUNK  ((N_NODES + SCAN_BLOCKS - 1) / SCAN_BLOCKS)
__device__ int g_bsum[SCAN_BLOCKS];

// ---------------- init ----------------
__global__ void k_init() {
    int i = blockIdx.x * blockDim.x + threadIdx.x;
    if (i < N_NODES) g_cnt[i] = 0;
    if (i < HC) { g_colsum[i] = 0.0f; g_colsum2[i] = 0.0f; }
}

// ---------------- convert kernels ----------------
__global__ void k_conv_a(const float* __restrict__ X) {
    size_t i = (size_t)blockIdx.x * blockDim.x + threadIdx.x;
    if (i * 4 >= (size_t)N_NODES * F_IN) return;
    float4 v = ((const float4*)X)[i];
    __half2* o = (__half2*)g_af;
    o[i * 2 + 0] = __floats2half2_rn(v.x, v.y);
    o[i * 2 + 1] = __floats2half2_rn(v.z, v.w);
}

__global__ void k_conv_bt(const float* __restrict__ W) {
    int idx = blockIdx.x * blockDim.x + threadIdx.x;
    if (idx >= F_IN * HC) return;
    int k = idx >> 9, n = idx & (HC - 1);
    g_bf[(size_t)n * F_IN + k] = __float2half(W[idx]);
}

__global__ void k_conv_wg(const float* __restrict__ W) {
    int idx = blockIdx.x * blockDim.x + threadIdx.x;
    if (idx >= HC * HID) return;
    int k = idx >> 6, n = idx & (HID - 1);
    g_wgf[(size_t)n * HC + k] = __float2half(W[idx]);
}

// BN-final (inlined) + BN apply + ReLU + fp16 convert. Block = 64 rows.
__global__ void __launch_bounds__(256)
k_conv_xr(const float* __restrict__ gamma, const float* __restrict__ beta) {
    __shared__ float ssc[HC], ssh[HC];
    int t = threadIdx.x;
    for (int c = t; c < HC; c += 256) {
        float mean = g_colsum[c] * (1.0f / N_NODES);
        float var  = g_colsum2[c] * (1.0f / N_NODES) - mean * mean;
        float sc = gamma[c] * rsqrtf(var + 1e-5f);
        ssc[c] = sc;
        ssh[c] = beta[c] - mean * sc;
    }
    __syncthreads();
    int row0 = blockIdx.x * 64;
    for (int idx = t; idx < 64 * 128; idx += 256) {
        int r = row0 + (idx >> 7);
        if (r >= N_NODES) break;
        int cc = (idx & 127) * 4;
        const __half2* ip = (const __half2*)&g_out1h[(size_t)r * HC + cc];
        float2 v01 = __half22float2(ip[0]);
        float2 v23 = __half22float2(ip[1]);
        v01.x = fmaxf(fmaf(v01.x, ssc[cc + 0], ssh[cc + 0]), 0.0f);
        v01.y = fmaxf(fmaf(v01.y, ssc[cc + 1], ssh[cc + 1]), 0.0f);
        v23.x = fmaxf(fmaf(v23.x, ssc[cc + 2], ssh[cc + 2]), 0.0f);
        v23.y = fmaxf(fmaf(v23.y, ssc[cc + 3], ssh[cc + 3]), 0.0f);
        __half2* o = (__half2*)&g_xr[(size_t)r * HC + cc];
        o[0] = __floats2half2_rn(v01.x, v01.y);
        o[1] = __floats2half2_rn(v23.x, v23.y);
    }
}

// ========== shared mma helpers ==========
#define SA 72

__device__ __forceinline__ void mma16816(float* c, const unsigned* a, unsigned b0, unsigned b1) {
    asm volatile(
        "mma.sync.aligned.m16n8k16.row.col.f32.f16.f16.f32 "
        "{%0,%1,%2,%3}, {%4,%5,%6,%7}, {%8,%9}, {%0,%1,%2,%3};\n"
        : "+f"(c[0]), "+f"(c[1]), "+f"(c[2]), "+f"(c[3])
        : "r"(a[0]), "r"(a[1]), "r"(a[2]), "r"(a[3]), "r"(b0), "r"(b1));
}

__device__ __forceinline__ void ldsm4(unsigned* r, const __half* p) {
    unsigned a = (unsigned)__cvta_generic_to_shared(p);
    asm volatile("ldmatrix.sync.aligned.m8n8.x4.shared.b16 {%0,%1,%2,%3}, [%4];\n"
                 : "=r"(r[0]), "=r"(r[1]), "=r"(r[2]), "=r"(r[3]) : "r"(a));
}

__device__ __forceinline__ void cpa16(void* dst, const void* src, int sz) {
    unsigned d = (unsigned)__cvta_generic_to_shared(dst);
    asm volatile("cp.async.cg.shared.global [%0], [%1], 16, %2;\n"
                 :: "r"(d), "l"(src), "r"(sz));
}

// ========== GEMM1: fp16 mma, 128x128 tiles, BK=64, 2 CTAs/SM, fused att dots ==========
#define BM 128
#define BN 128
#define BK 64
#define A_ST   (BM * SA)
#define B_ST   (BN * SA)
#define STAGE_ELEMS (A_ST + B_ST)
#define GEMM1_SMEM (2 * STAGE_ELEMS * 2 + 3072)

__global__ void __launch_bounds__(256, 2)
k_gemm1(const float* __restrict__ att_src, const float* __restrict__ att_dst) {
    extern __shared__ __half sm[];
    float* satt = (float*)(sm + 2 * STAGE_ELEMS);
    float* sred = satt + 256;

    int tid  = threadIdx.x;
    int warp = tid >> 5, lane = tid & 31;
    int head = blockIdx.x;
    int row0 = blockIdx.y * BM, col0 = head * BN;
    int wm = (warp >> 1) * 32, wn = (warp & 1) * 64;

    for (int i = tid; i < CH; i += 256) {
        satt[i]      = att_src[head * CH + i];
        satt[CH + i] = att_dst[head * CH + i];
    }

    float acc[2][8][4];
#pragma unroll
    for (int t = 0; t < 2; t++)
#pragma unroll
        for (int n = 0; n < 8; n++)
#pragma unroll
            for (int j = 0; j < 4; j++) acc[t][n][j] = 0.0f;

    int lrow = tid >> 1, lch0 = (tid & 1) * 4;
    int gra = row0 + lrow;
    int asz = (gra < N_NODES) ? 16 : 0;
    size_t asrc = (size_t)min(gra, N_NODES - 1) * F_IN + lch0 * 8;
    size_t bsrc = (size_t)(col0 + lrow) * F_IN + lch0 * 8;
    int sOff = lrow * SA + lch0 * 8;

    const int NIT = F_IN / BK;

    __half* st[2];
    st[0] = sm;
    st[1] = sm + STAGE_ELEMS;

    int aRow = lane & 15;
    int aK   = (lane >> 4) << 3;
    int bRow = ((lane >> 4) << 3) + (lane & 7);
    int bK   = ((lane >> 3) & 1) << 3;

    {
        __half* s = st[0];
#pragma unroll
        for (int c = 0; c < 4; c++) {
            cpa16(s + sOff + c * 8,        g_af + asrc + c * 8, asz);
            cpa16(s + A_ST + sOff + c * 8, g_bf + bsrc + c * 8, 16);
        }
        asm volatile("cp.async.commit_group;\n");
    }

    for (int it = 0; it < NIT; it++) {
        if (it + 1 < NIT) {
            int k0 = (it + 1) * BK;
            __half* s = st[(it + 1) & 1];
#pragma unroll
            for (int c = 0; c < 4; c++) {
                cpa16(s + sOff + c * 8,        g_af + asrc + k0 + c * 8, asz);
                cpa16(s + A_ST + sOff + c * 8, g_bf + bsrc + k0 + c * 8, 16);
            }
        }
        asm volatile("cp.async.commit_group;\n");
        asm volatile("cp.async.wait_group 1;\n");
        __syncthreads();

        const __half* pA = st[it & 1];
        const __half* pB = pA + A_ST;

#pragma unroll
        for (int kk = 0; kk < BK; kk += 16) {
            unsigned af[2][4];
            ldsm4(af[0], pA + (wm +  0 + aRow) * SA + kk + aK);
            ldsm4(af[1], pA + (wm + 16 + aRow) * SA + kk + aK);
#pragma unroll
            for (int p = 0; p < 4; p++) {
                unsigned bf[4];
                ldsm4(bf, pB + (wn + p * 16 + bRow) * SA + kk + bK);
                int n0 = 2 * p, n1 = 2 * p + 1;
                mma16816(acc[0][n0], af[0], bf[0], bf[1]);
                mma16816(acc[1][n0], af[1], bf[0], bf[1]);
                mma16816(acc[0][n1], af[0], bf[2], bf[3]);
                mma16816(acc[1][n1], af[1], bf[2], bf[3]);
            }
        }
        __syncthreads();
    }

    // ---- epilogue 1: store h (fp16) ----
    int g = lane >> 2, tig = lane & 3;
#pragma unroll
    for (int t = 0; t < 2; t++) {
        int r0 = row0 + wm + t * 16 + g;
#pragma unroll
        for (int n = 0; n < 8; n++) {
            int cc = col0 + wn + n * 8 + tig * 2;
            if (r0 < N_NODES)
                *(__half2*)&g_hh[(size_t)r0 * HC + cc] = __floats2half2_rn(acc[t][n][0], acc[t][n][1]);
            if (r0 + 8 < N_NODES)
                *(__half2*)&g_hh[(size_t)(r0 + 8) * HC + cc] = __floats2half2_rn(acc[t][n][2], acc[t][n][3]);
        }
    }

    // ---- epilogue 2: fused attention dots ----
    float ps[4] = {0.f, 0.f, 0.f, 0.f};
    float pd[4] = {0.f, 0.f, 0.f, 0.f};
#pragma unroll
    for (int t = 0; t < 2; t++) {
#pragma unroll
        for (int n = 0; n < 8; n++) {
            int cc = wn + n * 8 + tig * 2;
            float a0s = satt[cc],      a1s = satt[cc + 1];
            float a0d = satt[CH + cc], a1d = satt[CH + cc + 1];
            ps[t * 2 + 0] += acc[t][n][0] * a0s + acc[t][n][1] * a1s;
            pd[t * 2 + 0] += acc[t][n][0] * a0d + acc[t][n][1] * a1d;
            ps[t * 2 + 1] += acc[t][n][2] * a0s + acc[t][n][3] * a1s;
            pd[t * 2 + 1] += acc[t][n][2] * a0d + acc[t][n][3] * a1d;
        }
    }
#pragma unroll
    for (int o = 1; o <= 2; o <<= 1) {
#pragma unroll
        for (int rc = 0; rc < 4; rc++) {
            ps[rc] += __shfl_xor_sync(0xFFFFFFFFu, ps[rc], o);
            pd[rc] += __shfl_xor_sync(0xFFFFFFFFu, pd[rc], o);
        }
    }
    __syncthreads();
    if (tig == 0) {
#pragma unroll
        for (int rc = 0; rc < 4; rc++) {
            int e = ((warp * 8 + g) * 4 + rc) * 2;
            sred[e + 0] = ps[rc];
            sred[e + 1] = pd[rc];
        }
    }
    __syncthreads();
    if (tid < 128) {
        int wpair = tid >> 5, gg = (tid >> 2) & 7, rc = tid & 3;
        int w0 = wpair * 2, w1 = w0 + 1;
        int e0 = ((w0 * 8 + gg) * 4 + rc) * 2;
        int e1 = ((w1 * 8 + gg) * 4 + rc) * 2;
        int row = row0 + wpair * 32 + rc * 8 + gg;
        if (row < N_NODES) {
            g_asrc[row * 4 + head] = sred[e0 + 0] + sred[e1 + 0];
            g_adst[row * 4 + head] = sred[e0 + 1] + sred[e1 + 1];
        }
    }
}

// ========== GEMM2: fp16 mma, 128x64 tiles, BK=64, 2 CTAs/SM ==========
#define B2_ST  (64 * SA)
#define STAGE2 (A_ST + B2_ST)
#define GEMM2_SMEM (2 * STAGE2 * 2)

__global__ void __launch_bounds__(256, 2)
k_gemm2() {
    extern __shared__ __half sm[];

    int tid  = threadIdx.x;
    int warp = tid >> 5, lane = tid & 31;
    int row0 = blockIdx.x * BM;
    int wm = (warp >> 1) * 32, wn = (warp & 1) * 32;

    float acc[2][4][4];
#pragma unroll
    for (int t = 0; t < 2; t++)
#pragma unroll
        for (int n = 0; n < 4; n++)
#pragma unroll
            for (int j = 0; j < 4; j++) acc[t][n][j] = 0.0f;

    int lrow = tid >> 1, lch0 = (tid & 1) * 4;
    int gra = row0 + lrow;
    int asz = (gra < N_NODES) ? 16 : 0;
    size_t asrc = (size_t)min(gra, N_NODES - 1) * HC + lch0 * 8;
    int sOffA = lrow * SA + lch0 * 8;
    int brow = tid >> 2, bch0 = (tid & 3) * 2;
    size_t bsrc = (size_t)brow * HC + bch0 * 8;
    int sOffB = brow * SA + bch0 * 8;

    const int NIT = HC / BK;

    __half* st[2];
    st[0] = sm;
    st[1] = sm + STAGE2;

    int aRow = lane & 15;
    int aK   = (lane >> 4) << 3;
    int bRow = ((lane >> 4) << 3) + (lane & 7);
    int bK   = ((lane >> 3) & 1) << 3;

    {
        __half* s = st[0];
#pragma unroll
        for (int c = 0; c < 4; c++)
            cpa16(s + sOffA + c * 8, g_xr + asrc + c * 8, asz);
#pragma unroll
        for (int c = 0; c < 2; c++)
            cpa16(s + A_ST + sOffB + c * 8, g_wgf + bsrc + c * 8, 16);
        asm volatile("cp.async.commit_group;\n");
    }

    for (int it = 0; it < NIT; it++) {
        if (it + 1 < NIT) {
            int k0 = (it + 1) * BK;
            __half* s = st[(it + 1) & 1];
#pragma unroll
            for (int c = 0; c < 4; c++)
                cpa16(s + sOffA + c * 8, g_xr + asrc + k0 + c * 8, asz);
#pragma unroll
            for (int c = 0; c < 2; c++)
                cpa16(s + A_ST + sOffB + c * 8, g_wgf + bsrc + k0 + c * 8, 16);
        }
        asm volatile("cp.async.commit_group;\n");
        asm volatile("cp.async.wait_group 1;\n");
        __syncthreads();

        const __half* pA = st[it & 1];
        const __half* pB = pA + A_ST;

#pragma unroll
        for (int kk = 0; kk < BK; kk += 16) {
            unsigned af[2][4];
            ldsm4(af[0], pA + (wm +  0 + aRow) * SA + kk + aK);
            ldsm4(af[1], pA + (wm + 16 + aRow) * SA + kk + aK);
#pragma unroll
            for (int p = 0; p < 2; p++) {
                unsigned bf[4];
                ldsm4(bf, pB + (wn + p * 16 + bRow) * SA + kk + bK);
                int n0 = 2 * p, n1 = 2 * p + 1;
                mma16816(acc[0][n0], af[0], bf[0], bf[1]);
                mma16816(acc[1][n0], af[1], bf[0], bf[1]);
                mma16816(acc[0][n1], af[0], bf[2], bf[3]);
                mma16816(acc[1][n1], af[1], bf[2], bf[3]);
            }
        }
        __syncthreads();
    }

    int g = lane >> 2, tig = lane & 3;
#pragma unroll
    for (int t = 0; t < 2; t++) {
        int r0 = row0 + wm + t * 16 + g;
#pragma unroll
        for (int n = 0; n < 4; n++) {
            int cc = wn + n * 8 + tig * 2;
            if (r0 < N_NODES)
                *(__half2*)&g_h2h[(size_t)r0 * HID + cc] = __floats2half2_rn(acc[t][n][0], acc[t][n][1]);
            if (r0 + 8 < N_NODES)
                *(__half2*)&g_h2h[(size_t)(r0 + 8) * HID + cc] = __floats2half2_rn(acc[t][n][2], acc[t][n][3]);
        }
    }
}

// ---------------- CSR build ----------------
__global__ void k_count(const int* __restrict__ ei, int E) {
    int e = blockIdx.x * blockDim.x + threadIdx.x;
    int ET = E + N_NODES;
    if (e >= ET) return;
    int d = (e < E) ? ei[E + e] : (e - E);
    atomicAdd(&g_cnt[d], 1);
}

__global__ void k_scan1() {
    __shared__ int red[8];
    int b = blockIdx.x, t = threadIdx.x;
    int lo = b * SCAN_CHUNK, hi = min(lo + SCAN_CHUNK, N_NODES);
    int s = 0;
    for (int i = lo + t; i < hi; i += 256) s += g_cnt[i];
#pragma unroll
    for (int o = 16; o > 0; o >>= 1) s += __shfl_xor_sync(0xFFFFFFFFu, s, o);
    if ((t & 31) == 0) red[t >> 5] = s;
    __syncthreads();
    if (t == 0) {
        int tot = 0;
#pragma unroll
        for (int i = 0; i < 8; i++) tot += red[i];
        g_bsum[b] = tot;
    }
}

__global__ void k_scan2() {
    __shared__ int sh[128];
    int t = threadIdx.x;
    int v = (t < SCAN_BLOCKS) ? g_bsum[t] : 0;
    sh[t] = v;
    __syncthreads();
#pragma unroll
    for (int o = 1; o < 128; o <<= 1) {
        int x = (t >= o) ? sh[t - o] : 0;
        __syncthreads();
        sh[t] += x;
        __syncthreads();
    }
    if (t < SCAN_BLOCKS) g_bsum[t] = sh[t] - v;
    if (t == 127) g_off[N_NODES] = sh[127];
}

__global__ void k_scan3() {
    __shared__ int sh[256];
    int b = blockIdx.x, t = threadIdx.x;
    int lo = b * SCAN_CHUNK;
    int i = lo + t;
    int v = (t < SCAN_CHUNK && i < N_NODES) ? g_cnt[i] : 0;
    sh[t] = v;
    __syncthreads();
#pragma unroll
    for (int o = 1; o < 256; o <<= 1) {
        int x = (t >= o) ? sh[t - o] : 0;
        __syncthreads();
        sh[t] += x;
        __syncthreads();
    }
    if (t < SCAN_CHUNK && i < N_NODES) {
        g_off[i] = g_bsum[b] + sh[t] - v;
        g_cnt[i] = 0;
    }
}

__global__ void k_fill(const int* __restrict__ ei, const float* __restrict__ ew, int E) {
    int e = blockIdx.x * blockDim.x + threadIdx.x;
    int ET = E + N_NODES;
    if (e >= ET) return;
    int s, d; float w;
    if (e < E) { s = ei[e]; d = ei[E + e]; w = ew[e]; }
    else       { s = d = e - E; w = 1.0f; }
    int slot = g_off[d] + atomicAdd(&g_cnt[d], 1);
    g_esrc[slot] = s;
    g_ewc[slot]  = w;
}

// ---------------- fused segment softmax + weighted degree (warp per node) ----------------
__global__ void k_softmax() {
    int d    = (blockIdx.x * blockDim.x + threadIdx.x) >> 5;
    int lane = threadIdx.x & 31;
    if (d >= N_NODES) return;
    int beg = g_off[d], end = g_off[d + 1];
    int cnt = end - beg;
    float4 ad = *(const float4*)&g_adst[d * 4];

    float mx0 = -1e30f, mx1 = -1e30f, mx2 = -1e30f, mx3 = -1e30f;
    float degw = 0.0f;

    if (cnt <= 32) {
        int i = beg + lane;
        bool act = lane < cnt;
        float l0 = -1e30f, l1 = -1e30f, l2 = -1e30f, l3 = -1e30f;
        if (act) {
            int s = g_esrc[i];
            float4 as = *(const float4*)&g_asrc[s * 4];
            l0 = as.x + ad.x; l1 = as.y + ad.y; l2 = as.z + ad.z; l3 = as.w + ad.w;
            l0 = l0 > 0.f ? l0 : 0.2f * l0;
            l1 = l1 > 0.f ? l1 : 0.2f * l1;
            l2 = l2 > 0.f ? l2 : 0.2f * l2;
            l3 = l3 > 0.f ? l3 : 0.2f * l3;
            degw = g_ewc[i];
        }
        mx0 = l0; mx1 = l1; mx2 = l2; mx3 = l3;
#pragma unroll
        for (int o = 16; o > 0; o >>= 1) {
            mx0 = fmaxf(mx0, __shfl_xor_sync(0xFFFFFFFFu, mx0, o));
            mx1 = fmaxf(mx1, __shfl_xor_sync(0xFFFFFFFFu, mx1, o));
            mx2 = fmaxf(mx2, __shfl_xor_sync(0xFFFFFFFFu, mx2, o));
            mx3 = fmaxf(mx3, __shfl_xor_sync(0xFFFFFFFFu, mx3, o));
            degw += __shfl_xor_sync(0xFFFFFFFFu, degw, o);
        }
        float e0 = act ? __expf(l0 - mx0) : 0.f;
        float e1 = act ? __expf(l1 - mx1) : 0.f;
        float e2 = act ? __expf(l2 - mx2) : 0.f;
        float e3 = act ? __expf(l3 - mx3) : 0.f;
        float s0 = e0, s1 = e1, s2 = e2, s3 = e3;
#pragma unroll
        for (int o = 16; o > 0; o >>= 1) {
            s0 += __shfl_xor_sync(0xFFFFFFFFu, s0, o);
            s1 += __shfl_xor_sync(0xFFFFFFFFu, s1, o);
            s2 += __shfl_xor_sync(0xFFFFFFFFu, s2, o);
            s3 += __shfl_xor_sync(0xFFFFFFFFu, s3, o);
        }
        if (act) {
            float4 al = make_float4(e0 / (s0 + 1e-16f), e1 / (s1 + 1e-16f),
                                    e2 / (s2 + 1e-16f), e3 / (s3 + 1e-16f));
            *(float4*)&g_alpha[(size_t)i * 4] = al;
        }
    } else {
        for (int i = beg + lane; i < end; i += 32) {
            int s = g_esrc[i];
            float4 as = *(const float4*)&g_asrc[s * 4];
            float l0 = as.x + ad.x, l1 = as.y + ad.y, l2 = as.z + ad.z, l3 = as.w + ad.w;
            l0 = l0 > 0.f ? l0 : 0.2f * l0;
            l1 = l1 > 0.f ? l1 : 0.2f * l1;
            l2 = l2 > 0.f ? l2 : 0.2f * l2;
            l3 = l3 > 0.f ? l3 : 0.2f * l3;
            *(float4*)&g_alpha[(size_t)i * 4] = make_float4(l0, l1, l2, l3);
            mx0 = fmaxf(mx0, l0); mx1 = fmaxf(mx1, l1);
            mx2 = fmaxf(mx2, l2); mx3 = fmaxf(mx3, l3);
            degw += g_ewc[i];
        }
#pragma unroll
        for (int o = 16; o > 0; o >>= 1) {
            mx0 = fmaxf(mx0, __shfl_xor_sync(0xFFFFFFFFu, mx0, o));
            mx1 = fmaxf(mx1, __shfl_xor_sync(0xFFFFFFFFu, mx1, o));
            mx2 = fmaxf(mx2, __shfl_xor_sync(0xFFFFFFFFu, mx2, o));
            mx3 = fmaxf(mx3, __shfl_xor_sync(0xFFFFFFFFu, mx3, o));
            degw += __shfl_xor_sync(0xFFFFFFFFu, degw, o);
        }
        float s0 = 0.f, s1 = 0.f, s2 = 0.f, s3 = 0.f;
        for (int i = beg + lane; i < end; i += 32) {
            float4 l = *(const float4*)&g_alpha[(size_t)i * 4];
            float e0 = __expf(l.x - mx0), e1 = __expf(l.y - mx1);
            float e2 = __expf(l.z - mx2), e3 = __expf(l.w - mx3);
            *(float4*)&g_alpha[(size_t)i * 4] = make_float4(e0, e1, e2, e3);
            s0 += e0; s1 += e1; s2 += e2; s3 += e3;
        }
#pragma unroll
        for (int o = 16; o > 0; o >>= 1) {
            s0 += __shfl_xor_sync(0xFFFFFFFFu, s0, o);
            s1 += __shfl_xor_sync(0xFFFFFFFFu, s1, o);
            s2 += __shfl_xor_sync(0xFFFFFFFFu, s2, o);
            s3 += __shfl_xor_sync(0xFFFFFFFFu, s3, o);
        }
        float r0 = 1.f / (s0 + 1e-16f), r1 = 1.f / (s1 + 1e-16f);
        float r2 = 1.f / (s2 + 1e-16f), r3 = 1.f / (s3 + 1e-16f);
        for (int i = beg + lane; i < end; i += 32) {
            float4 l = *(const float4*)&g_alpha[(size_t)i * 4];
            *(float4*)&g_alpha[(size_t)i * 4] = make_float4(l.x * r0, l.y * r1, l.z * r2, l.w * r3);
        }
    }
    if (lane == 0) g_dinv[d] = degw > 0.f ? rsqrtf(degw) : 0.0f;
}

// ---------------- GAT aggregation (per-node block, fp16 h, fp32 acc) ----------------
__global__ void __launch_bounds__(128)
k_aggregate(const float* __restrict__ b_gat) {
    int d = blockIdx.x;
    int tid = threadIdx.x;
    int head = tid >> 5;
    int c = tid * 4;
    float4 acc = *(const float4*)&b_gat[c];
    int beg = g_off[d], end = g_off[d + 1];
    int i = beg;
    for (; i + 1 < end; i += 2) {
        int s0 = g_esrc[i], s1 = g_esrc[i + 1];
        float a0 = g_alpha[(size_t)i * 4 + head];
        float a1 = g_alpha[(size_t)(i + 1) * 4 + head];
        const __half2* p0 = (const __half2*)&g_hh[(size_t)s0 * HC + c];
        const __half2* p1 = (const __half2*)&g_hh[(size_t)s1 * HC + c];
        float2 v0a = __half22float2(p0[0]), v0b = __half22float2(p0[1]);
        float2 v1a = __half22float2(p1[0]), v1b = __half22float2(p1[1]);
        acc.x = fmaf(v0a.x, a0, acc.x); acc.y = fmaf(v0a.y, a0, acc.y);
        acc.z = fmaf(v0b.x, a0, acc.z); acc.w = fmaf(v0b.y, a0, acc.w);
        acc.x = fmaf(v1a.x, a1, acc.x); acc.y = fmaf(v1a.y, a1, acc.y);
        acc.z = fmaf(v1b.x, a1, acc.z); acc.w = fmaf(v1b.y, a1, acc.w);
    }
    if (i < end) {
        int s0 = g_esrc[i];
        float a0 = g_alpha[(size_t)i * 4 + head];
        const __half2* p0 = (const __half2*)&g_hh[(size_t)s0 * HC + c];
        float2 v0a = __half22float2(p0[0]), v0b = __half22float2(p0[1]);
        acc.x = fmaf(v0a.x, a0, acc.x); acc.y = fmaf(v0a.y, a0, acc.y);
        acc.z = fmaf(v0b.x, a0, acc.z); acc.w = fmaf(v0b.y, a0, acc.w);
    }
    __half2* o = (__half2*)&g_out1h[(size_t)d * HC + c];
    o[0] = __floats2half2_rn(acc.x, acc.y);
    o[1] = __floats2half2_rn(acc.z, acc.w);
}

// ---------------- BN stats (fp16 in, fp32 accum) ----------------
__global__ void k_bnstats() {
    int col = threadIdx.x;
    float s = 0.f, s2 = 0.f;
    for (int r = blockIdx.x; r < N_NODES; r += gridDim.x) {
        float v = __half2float(g_out1h[(size_t)r * HC + col]);
        s += v; s2 += v * v;
    }
    atomicAdd(&g_colsum[col], s);
    atomicAdd(&g_colsum2[col], s2);
}

// ---------------- GCN gather (fp16 h2) ----------------
__global__ void k_gcn(const float* __restrict__ b_gcn, float* __restrict__ out) {
    int d    = (blockIdx.x * blockDim.x + threadIdx.x) >> 5;
    int lane = threadIdx.x & 31;
    if (d >= N_NODES) return;
    float dinv_d = g_dinv[d];
    float2 acc = *(const float2*)&b_gcn[lane * 2];
    int beg = g_off[d], end = g_off[d + 1];
    int i = beg;
    for (; i + 1 < end; i += 2) {
        int s0 = g_esrc[i], s1 = g_esrc[i + 1];
        float n0 = g_dinv[s0] * g_ewc[i] * dinv_d;
        float n1 = g_dinv[s1] * g_ewc[i + 1] * dinv_d;
        float2 v0 = __half22float2(*(const __half2*)&g_h2h[(size_t)s0 * HID + lane * 2]);
        float2 v1 = __half22float2(*(const __half2*)&g_h2h[(size_t)s1 * HID + lane * 2]);
        acc.x = fmaf(v0.x, n0, acc.x); acc.y = fmaf(v0.y, n0, acc.y);
        acc.x = fmaf(v1.x, n1, acc.x); acc.y = fmaf(v1.y, n1, acc.y);
    }
    if (i < end) {
        int s0 = g_esrc[i];
        float n0 = g_dinv[s0] * g_ewc[i] * dinv_d;
        float2 v0 = __half22float2(*(const __half2*)&g_h2h[(size_t)s0 * HID + lane * 2]);
        acc.x = fmaf(v0.x, n0, acc.x); acc.y = fmaf(v0.y, n0, acc.y);
    }
    *(float2*)&out[(size_t)d * HID + lane * 2] = acc;
}

// ---------------- launch ----------------
extern "C" void kernel_launch(void* const* d_in, const int* in_sizes, int n_in,
                              void* d_out, int out_size) {
    const float* x       = (const float*)d_in[0];
    const int*   ei      = (const int*)  d_in[1];
    const float* ew      = (const float*)d_in[2];
    const float* W_gat   = (const float*)d_in[3];
    const float* att_src = (const float*)d_in[4];
    const float* att_dst = (const float*)d_in[5];
    const float* b_gat   = (const float*)d_in[6];
    const float* gamma   = (const float*)d_in[7];
    const float* beta    = (const float*)d_in[8];
    const float* W_gcn   = (const float*)d_in[9];
    const float* b_gcn   = (const float*)d_in[10];
    float* out = (float*)d_out;

    int E  = in_sizes[1] / 2;
    int ET = E + N_NODES;

    static cudaStream_t s_side = nullptr;
    static cudaEvent_t ev_fork = nullptr, ev_join = nullptr;
    if (!s_side) {
        cudaFuncSetAttribute(k_gemm1, cudaFuncAttributeMaxDynamicSharedMemorySize, GEMM1_SMEM);
        cudaFuncSetAttribute(k_gemm2, cudaFuncAttributeMaxDynamicSharedMemorySize, GEMM2_SMEM);
        cudaStreamCreateWithFlags(&s_side, cudaStreamNonBlocking);
        cudaEventCreateWithFlags(&ev_fork, cudaEventDisableTiming);
        cudaEventCreateWithFlags(&ev_join, cudaEventDisableTiming);
    }

    // ---- fork: init + CSR build + W_gcn convert on side stream ----
    cudaEventRecord(ev_fork, 0);
    cudaStreamWaitEvent(s_side, ev_fork, 0);
    k_init<<<(N_NODES + 255) / 256, 256, 0, s_side>>>();
    k_count<<<(ET + 255) / 256, 256, 0, s_side>>>(ei, E);
    k_scan1<<<SCAN_BLOCKS, 256, 0, s_side>>>();
    k_scan2<<<1, 128, 0, s_side>>>();
    k_scan3<<<SCAN_BLOCKS, 256, 0, s_side>>>();
    k_fill<<<(ET + 255) / 256, 256, 0, s_side>>>(ei, ew, E);
    k_conv_wg<<<(HC * HID + 255) / 256, 256, 0, s_side>>>(W_gcn);
    cudaEventRecord(ev_join, s_side);

    // ---- main stream ----
    k_conv_a<<<((N_NODES * (F_IN / 4)) + 255) / 256, 256>>>(x);
    k_conv_bt<<<(F_IN * HC + 255) / 256, 256>>>(W_gat);

    dim3 g1(HC / BN, (N_NODES + BM - 1) / BM);   // (4, 235)
    k_gemm1<<<g1, 256, GEMM1_SMEM>>>(att_src, att_dst);

    cudaStreamWaitEvent(0, ev_join, 0);
    k_softmax<<<(N_NODES * 32 + 255) / 256, 256>>>();
    k_aggregate<<<N_NODES, 128>>>(b_gat);

    k_bnstats<<<240, 512>>>();
    k_conv_xr<<<(N_NODES + 63) / 64, 256>>>(gamma, beta);

    k_gemm2<<<(N_NODES + BM - 1) / BM, 256, GEMM2_SMEM>>>();
    k_gcn<<<(N_NODES * 32 + 255) / 256, 256>>>(b_gcn, out);
}

// round 16
// speedup vs baseline: 1.0928x; 1.0523x over previous
#include <cuda_runtime.h>
#include <cuda_fp16.h>
#include <cstdint>
#include <math.h>

#define N_NODES 30000
#define E_MAX   480000
#define ET_MAX  (E_MAX + N_NODES)
#define F_IN    1280
#define HEADS   4
#define CH      128
#define HC      512
#define HID     64

// ---------------- scratch ----------------
__device__ __half g_hh[(size_t)N_NODES * HC];    // GAT features (fp16)
__device__ __half g_out1h[(size_t)N_NODES * HC]; // GAT output (fp16)
__device__ __half g_xr[(size_t)N_NODES * HC];    // relu(bn(out1)) fp16
__device__ float g_asrc[N_NODES * HEADS];
__device__ float g_adst[N_NODES * HEADS];
__device__ float g_alpha[(size_t)ET_MAX * HEADS];
__device__ __half g_h2h[(size_t)N_NODES * HID];  // xr @ W_gcn (fp16)
__device__ float g_dinv[N_NODES];
__device__ float g_colsum[HC];
__device__ float g_colsum2[HC];
// CSR
__device__ int   g_cnt[N_NODES];
__device__ int   g_off[N_NODES + 1];
__device__ int   g_esrc[ET_MAX];
__device__ float g_ewc[ET_MAX];
// fp16 operands
__device__ __half g_af[(size_t)N_NODES * F_IN];
__device__ __half g_bf[(size_t)HC * F_IN];       // W_gat^T: [n][k]
__device__ __half g_wgf[(size_t)HID * HC];       // W_gcn^T: [n][k]
// scan partials
#define SCAN_BLOCKS 120
#define SCAN_CHUNK  ((N_NODES + SCAN_BLOCKS - 1) / SCAN_BLOCKS)
__device__ int g_bsum[SCAN_BLOCKS];

// ---------------- init ----------------
__global__ void k_init() {
    int i = blockIdx.x * blockDim.x + threadIdx.x;
    if (i < N_NODES) g_cnt[i] = 0;
    if (i < HC) { g_colsum[i] = 0.0f; g_colsum2[i] = 0.0f; }
}

// ---------------- convert kernels ----------------
__global__ void k_conv_a(const float* __restrict__ X) {
    size_t i = (size_t)blockIdx.x * blockDim.x + threadIdx.x;
    if (i * 4 >= (size_t)N_NODES * F_IN) return;
    float4 v = ((const float4*)X)[i];
    __half2* o = (__half2*)g_af;
    o[i * 2 + 0] = __floats2half2_rn(v.x, v.y);
    o[i * 2 + 1] = __floats2half2_rn(v.z, v.w);
}

__global__ void k_conv_bt(const float* __restrict__ W) {
    int idx = blockIdx.x * blockDim.x + threadIdx.x;
    if (idx >= F_IN * HC) return;
    int k = idx >> 9, n = idx & (HC - 1);
    g_bf[(size_t)n * F_IN + k] = __float2half(W[idx]);
}

__global__ void k_conv_wg(const float* __restrict__ W) {
    int idx = blockIdx.x * blockDim.x + threadIdx.x;
    if (idx >= HC * HID) return;
    int k = idx >> 6, n = idx & (HID - 1);
    g_wgf[(size_t)n * HC + k] = __float2half(W[idx]);
}

// BN-final (inlined) + BN apply + ReLU + fp16 convert. Block = 64 rows.
__global__ void __launch_bounds__(256)
k_conv_xr(const float* __restrict__ gamma, const float* __restrict__ beta) {
    __shared__ float ssc[HC], ssh[HC];
    int t = threadIdx.x;
    for (int c = t; c < HC; c += 256) {
        float mean = g_colsum[c] * (1.0f / N_NODES);
        float var  = g_colsum2[c] * (1.0f / N_NODES) - mean * mean;
        float sc = gamma[c] * rsqrtf(var + 1e-5f);
        ssc[c] = sc;
        ssh[c] = beta[c] - mean * sc;
    }
    __syncthreads();
    int row0 = blockIdx.x * 64;
    for (int idx = t; idx < 64 * 128; idx += 256) {
        int r = row0 + (idx >> 7);
        if (r >= N_NODES) break;
        int cc = (idx & 127) * 4;
        const __half2* ip = (const __half2*)&g_out1h[(size_t)r * HC + cc];
        float2 v01 = __half22float2(ip[0]);
        float2 v23 = __half22float2(ip[1]);
        v01.x = fmaxf(fmaf(v01.x, ssc[cc + 0], ssh[cc + 0]), 0.0f);
        v01.y = fmaxf(fmaf(v01.y, ssc[cc + 1], ssh[cc + 1]), 0.0f);
        v23.x = fmaxf(fmaf(v23.x, ssc[cc + 2], ssh[cc + 2]), 0.0f);
        v23.y = fmaxf(fmaf(v23.y, ssc[cc + 3], ssh[cc + 3]), 0.0f);
        __half2* o = (__half2*)&g_xr[(size_t)r * HC + cc];
        o[0] = __floats2half2_rn(v01.x, v01.y);
        o[1] = __floats2half2_rn(v23.x, v23.y);
    }
}

// ========== shared mma helpers ==========
#define SA 72

__device__ __forceinline__ void mma16816(float* c, const unsigned* a, unsigned b0, unsigned b1) {
    asm volatile(
        "mma.sync.aligned.m16n8k16.row.col.f32.f16.f16.f32 "
        "{%0,%1,%2,%3}, {%4,%5,%6,%7}, {%8,%9}, {%0,%1,%2,%3};\n"
        : "+f"(c[0]), "+f"(c[1]), "+f"(c[2]), "+f"(c[3])
        : "r"(a[0]), "r"(a[1]), "r"(a[2]), "r"(a[3]), "r"(b0), "r"(b1));
}

__device__ __forceinline__ void ldsm4(unsigned* r, const __half* p) {
    unsigned a = (unsigned)__cvta_generic_to_shared(p);
    asm volatile("ldmatrix.sync.aligned.m8n8.x4.shared.b16 {%0,%1,%2,%3}, [%4];\n"
                 : "=r"(r[0]), "=r"(r[1]), "=r"(r[2]), "=r"(r[3]) : "r"(a));
}

__device__ __forceinline__ void cpa16(void* dst, const void* src, int sz) {
    unsigned d = (unsigned)__cvta_generic_to_shared(dst);
    asm volatile("cp.async.ca.shared.global [%0], [%1], 16, %2;\n"
                 :: "r"(d), "l"(src), "r"(sz));
}

// ========== GEMM1: fp16 mma, 128x128 tiles, BK=64, 2 CTAs/SM, fused att dots ==========
#define BM 128
#define BN 128
#define BK 64
#define A_ST   (BM * SA)
#define B_ST   (BN * SA)
#define STAGE_ELEMS (A_ST + B_ST)
#define GEMM1_SMEM (2 * STAGE_ELEMS * 2 + 3072)

__global__ void __launch_bounds__(256, 2)
k_gemm1(const float* __restrict__ att_src, const float* __restrict__ att_dst) {
    extern __shared__ __half sm[];
    float* satt = (float*)(sm + 2 * STAGE_ELEMS);
    float* sred = satt + 256;

    int tid  = threadIdx.x;
    int warp = tid >> 5, lane = tid & 31;
    int head = blockIdx.x;
    int row0 = blockIdx.y * BM, col0 = head * BN;
    int wm = (warp >> 1) * 32, wn = (warp & 1) * 64;

    for (int i = tid; i < CH; i += 256) {
        satt[i]      = att_src[head * CH + i];
        satt[CH + i] = att_dst[head * CH + i];
    }

    float acc[2][8][4];
#pragma unroll
    for (int t = 0; t < 2; t++)
#pragma unroll
        for (int n = 0; n < 8; n++)
#pragma unroll
            for (int j = 0; j < 4; j++) acc[t][n][j] = 0.0f;

    int lrow = tid >> 1, lch0 = (tid & 1) * 4;
    int gra = row0 + lrow;
    int asz = (gra < N_NODES) ? 16 : 0;
    size_t asrc = (size_t)min(gra, N_NODES - 1) * F_IN + lch0 * 8;
    size_t bsrc = (size_t)(col0 + lrow) * F_IN + lch0 * 8;
    int sOff = lrow * SA + lch0 * 8;

    const int NIT = F_IN / BK;

    __half* st[2];
    st[0] = sm;
    st[1] = sm + STAGE_ELEMS;

    int aRow = lane & 15;
    int aK   = (lane >> 4) << 3;
    int bRow = ((lane >> 4) << 3) + (lane & 7);
    int bK   = ((lane >> 3) & 1) << 3;

    {
        __half* s = st[0];
#pragma unroll
        for (int c = 0; c < 4; c++) {
            cpa16(s + sOff + c * 8,        g_af + asrc + c * 8, asz);
            cpa16(s + A_ST + sOff + c * 8, g_bf + bsrc + c * 8, 16);
        }
        asm volatile("cp.async.commit_group;\n");
    }

    for (int it = 0; it < NIT; it++) {
        if (it + 1 < NIT) {
            int k0 = (it + 1) * BK;
            __half* s = st[(it + 1) & 1];
#pragma unroll
            for (int c = 0; c < 4; c++) {
                cpa16(s + sOff + c * 8,        g_af + asrc + k0 + c * 8, asz);
                cpa16(s + A_ST + sOff + c * 8, g_bf + bsrc + k0 + c * 8, 16);
            }
        }
        asm volatile("cp.async.commit_group;\n");
        asm volatile("cp.async.wait_group 1;\n");
        __syncthreads();

        const __half* pA = st[it & 1];
        const __half* pB = pA + A_ST;

#pragma unroll
        for (int kk = 0; kk < BK; kk += 16) {
            unsigned af[2][4];
            ldsm4(af[0], pA + (wm +  0 + aRow) * SA + kk + aK);
            ldsm4(af[1], pA + (wm + 16 + aRow) * SA + kk + aK);
#pragma unroll
            for (int p = 0; p < 4; p++) {
                unsigned bf[4];
                ldsm4(bf, pB + (wn + p * 16 + bRow) * SA + kk + bK);
                int n0 = 2 * p, n1 = 2 * p + 1;
                mma16816(acc[0][n0], af[0], bf[0], bf[1]);
                mma16816(acc[1][n0], af[1], bf[0], bf[1]);
                mma16816(acc[0][n1], af[0], bf[2], bf[3]);
                mma16816(acc[1][n1], af[1], bf[2], bf[3]);
            }
        }
        __syncthreads();
    }

    // ---- epilogue 1: store h (fp16) ----
    int g = lane >> 2, tig = lane & 3;
#pragma unroll
    for (int t = 0; t < 2; t++) {
        int r0 = row0 + wm + t * 16 + g;
#pragma unroll
        for (int n = 0; n < 8; n++) {
            int cc = col0 + wn + n * 8 + tig * 2;
            if (r0 < N_NODES)
                *(__half2*)&g_hh[(size_t)r0 * HC + cc] = __floats2half2_rn(acc[t][n][0], acc[t][n][1]);
            if (r0 + 8 < N_NODES)
                *(__half2*)&g_hh[(size_t)(r0 + 8) * HC + cc] = __floats2half2_rn(acc[t][n][2], acc[t][n][3]);
        }
    }

    // ---- epilogue 2: fused attention dots ----
    float ps[4] = {0.f, 0.f, 0.f, 0.f};
    float pd[4] = {0.f, 0.f, 0.f, 0.f};
#pragma unroll
    for (int t = 0; t < 2; t++) {
#pragma unroll
        for (int n = 0; n < 8; n++) {
            int cc = wn + n * 8 + tig * 2;
            float a0s = satt[cc],      a1s = satt[cc + 1];
            float a0d = satt[CH + cc], a1d = satt[CH + cc + 1];
            ps[t * 2 + 0] += acc[t][n][0] * a0s + acc[t][n][1] * a1s;
            pd[t * 2 + 0] += acc[t][n][0] * a0d + acc[t][n][1] * a1d;
            ps[t * 2 + 1] += acc[t][n][2] * a0s + acc[t][n][3] * a1s;
            pd[t * 2 + 1] += acc[t][n][2] * a0d + acc[t][n][3] * a1d;
        }
    }
#pragma unroll
    for (int o = 1; o <= 2; o <<= 1) {
#pragma unroll
        for (int rc = 0; rc < 4; rc++) {
            ps[rc] += __shfl_xor_sync(0xFFFFFFFFu, ps[rc], o);
            pd[rc] += __shfl_xor_sync(0xFFFFFFFFu, pd[rc], o);
        }
    }
    __syncthreads();
    if (tig == 0) {
#pragma unroll
        for (int rc = 0; rc < 4; rc++) {
            int e = ((warp * 8 + g) * 4 + rc) * 2;
            sred[e + 0] = ps[rc];
            sred[e + 1] = pd[rc];
        }
    }
    __syncthreads();
    if (tid < 128) {
        int wpair = tid >> 5, gg = (tid >> 2) & 7, rc = tid & 3;
        int w0 = wpair * 2, w1 = w0 + 1;
        int e0 = ((w0 * 8 + gg) * 4 + rc) * 2;
        int e1 = ((w1 * 8 + gg) * 4 + rc) * 2;
        int row = row0 + wpair * 32 + rc * 8 + gg;
        if (row < N_NODES) {
            g_asrc[row * 4 + head] = sred[e0 + 0] + sred[e1 + 0];
            g_adst[row * 4 + head] = sred[e0 + 1] + sred[e1 + 1];
        }
    }
}

// ========== GEMM2: fp16 mma, 128x64 tiles, BK=64, 2 CTAs/SM ==========
#define B2_ST  (64 * SA)
#define STAGE2 (A_ST + B2_ST)
#define GEMM2_SMEM (2 * STAGE2 * 2)

__global__ void __launch_bounds__(256, 2)
k_gemm2() {
    extern __shared__ __half sm[];

    int tid  = threadIdx.x;
    int warp = tid >> 5, lane = tid & 31;
    int row0 = blockIdx.x * BM;
    int wm = (warp >> 1) * 32, wn = (warp & 1) * 32;

    float acc[2][4][4];
#pragma unroll
    for (int t = 0; t < 2; t++)
#pragma unroll
        for (int n = 0; n < 4; n++)
#pragma unroll
            for (int j = 0; j < 4; j++) acc[t][n][j] = 0.0f;

    int lrow = tid >> 1, lch0 = (tid & 1) * 4;
    int gra = row0 + lrow;
    int asz = (gra < N_NODES) ? 16 : 0;
    size_t asrc = (size_t)min(gra, N_NODES - 1) * HC + lch0 * 8;
    int sOffA = lrow * SA + lch0 * 8;
    int brow = tid >> 2, bch0 = (tid & 3) * 2;
    size_t bsrc = (size_t)brow * HC + bch0 * 8;
    int sOffB = brow * SA + bch0 * 8;

    const int NIT = HC / BK;

    __half* st[2];
    st[0] = sm;
    st[1] = sm + STAGE2;

    int aRow = lane & 15;
    int aK   = (lane >> 4) << 3;
    int bRow = ((lane >> 4) << 3) + (lane & 7);
    int bK   = ((lane >> 3) & 1) << 3;

    {
        __half* s = st[0];
#pragma unroll
        for (int c = 0; c < 4; c++)
            cpa16(s + sOffA + c * 8, g_xr + asrc + c * 8, asz);
#pragma unroll
        for (int c = 0; c < 2; c++)
            cpa16(s + A_ST + sOffB + c * 8, g_wgf + bsrc + c * 8, 16);
        asm volatile("cp.async.commit_group;\n");
    }

    for (int it = 0; it < NIT; it++) {
        if (it + 1 < NIT) {
            int k0 = (it + 1) * BK;
            __half* s = st[(it + 1) & 1];
#pragma unroll
            for (int c = 0; c < 4; c++)
                cpa16(s + sOffA + c * 8, g_xr + asrc + k0 + c * 8, asz);
#pragma unroll
            for (int c = 0; c < 2; c++)
                cpa16(s + A_ST + sOffB + c * 8, g_wgf + bsrc + k0 + c * 8, 16);
        }
        asm volatile("cp.async.commit_group;\n");
        asm volatile("cp.async.wait_group 1;\n");
        __syncthreads();

        const __half* pA = st[it & 1];
        const __half* pB = pA + A_ST;

#pragma unroll
        for (int kk = 0; kk < BK; kk += 16) {
            unsigned af[2][4];
            ldsm4(af[0], pA + (wm +  0 + aRow) * SA + kk + aK);
            ldsm4(af[1], pA + (wm + 16 + aRow) * SA + kk + aK);
#pragma unroll
            for (int p = 0; p < 2; p++) {
                unsigned bf[4];
                ldsm4(bf, pB + (wn + p * 16 + bRow) * SA + kk + bK);
                int n0 = 2 * p, n1 = 2 * p + 1;
                mma16816(acc[0][n0], af[0], bf[0], bf[1]);
                mma16816(acc[1][n0], af[1], bf[0], bf[1]);
                mma16816(acc[0][n1], af[0], bf[2], bf[3]);
                mma16816(acc[1][n1], af[1], bf[2], bf[3]);
            }
        }
        __syncthreads();
    }

    int g = lane >> 2, tig = lane & 3;
#pragma unroll
    for (int t = 0; t < 2; t++) {
        int r0 = row0 + wm + t * 16 + g;
#pragma unroll
        for (int n = 0; n < 4; n++) {
            int cc = wn + n * 8 + tig * 2;
            if (r0 < N_NODES)
                *(__half2*)&g_h2h[(size_t)r0 * HID + cc] = __floats2half2_rn(acc[t][n][0], acc[t][n][1]);
            if (r0 + 8 < N_NODES)
                *(__half2*)&g_h2h[(size_t)(r0 + 8) * HID + cc] = __floats2half2_rn(acc[t][n][2], acc[t][n][3]);
        }
    }
}

// ---------------- CSR build ----------------
__global__ void k_count(const int* __restrict__ ei, int E) {
    int e = blockIdx.x * blockDim.x + threadIdx.x;
    int ET = E + N_NODES;
    if (e >= ET) return;
    int d = (e < E) ? ei[E + e] : (e - E);
    atomicAdd(&g_cnt[d], 1);
}

__global__ void k_scan1() {
    __shared__ int red[8];
    int b = blockIdx.x, t = threadIdx.x;
    int lo = b * SCAN_CHUNK, hi = min(lo + SCAN_CHUNK, N_NODES);
    int s = 0;
    for (int i = lo + t; i < hi; i += 256) s += g_cnt[i];
#pragma unroll
    for (int o = 16; o > 0; o >>= 1) s += __shfl_xor_sync(0xFFFFFFFFu, s, o);
    if ((t & 31) == 0) red[t >> 5] = s;
    __syncthreads();
    if (t == 0) {
        int tot = 0;
#pragma unroll
        for (int i = 0; i < 8; i++) tot += red[i];
        g_bsum[b] = tot;
    }
}

__global__ void k_scan2() {
    __shared__ int sh[128];
    int t = threadIdx.x;
    int v = (t < SCAN_BLOCKS) ? g_bsum[t] : 0;
    sh[t] = v;
    __syncthreads();
#pragma unroll
    for (int o = 1; o < 128; o <<= 1) {
        int x = (t >= o) ? sh[t - o] : 0;
        __syncthreads();
        sh[t] += x;
        __syncthreads();
    }
    if (t < SCAN_BLOCKS) g_bsum[t] = sh[t] - v;
    if (t == 127) g_off[N_NODES] = sh[127];
}

__global__ void k_scan3() {
    __shared__ int sh[256];
    int b = blockIdx.x, t = threadIdx.x;
    int lo = b * SCAN_CHUNK;
    int i = lo + t;
    int v = (t < SCAN_CHUNK && i < N_NODES) ? g_cnt[i] : 0;
    sh[t] = v;
    __syncthreads();
#pragma unroll
    for (int o = 1; o < 256; o <<= 1) {
        int x = (t >= o) ? sh[t - o] : 0;
        __syncthreads();
        sh[t] += x;
        __syncthreads();
    }
    if (t < SCAN_CHUNK && i < N_NODES) {
        g_off[i] = g_bsum[b] + sh[t] - v;
        g_cnt[i] = 0;
    }
}

__global__ void k_fill(const int* __restrict__ ei, const float* __restrict__ ew, int E) {
    int e = blockIdx.x * blockDim.x + threadIdx.x;
    int ET = E + N_NODES;
    if (e >= ET) return;
    int s, d; float w;
    if (e < E) { s = ei[e]; d = ei[E + e]; w = ew[e]; }
    else       { s = d = e - E; w = 1.0f; }
    int slot = g_off[d] + atomicAdd(&g_cnt[d], 1);
    g_esrc[slot] = s;
    g_ewc[slot]  = w;
}

// ---------------- fused segment softmax + weighted degree (warp per node) ----------------
__global__ void k_softmax() {
    int d    = (blockIdx.x * blockDim.x + threadIdx.x) >> 5;
    int lane = threadIdx.x & 31;
    if (d >= N_NODES) return;
    int beg = g_off[d], end = g_off[d + 1];
    int cnt = end - beg;
    float4 ad = *(const float4*)&g_adst[d * 4];

    float mx0 = -1e30f, mx1 = -1e30f, mx2 = -1e30f, mx3 = -1e30f;
    float degw = 0.0f;

    if (cnt <= 32) {
        int i = beg + lane;
        bool act = lane < cnt;
        float l0 = -1e30f, l1 = -1e30f, l2 = -1e30f, l3 = -1e30f;
        if (act) {
            int s = g_esrc[i];
            float4 as = *(const float4*)&g_asrc[s * 4];
            l0 = as.x + ad.x; l1 = as.y + ad.y; l2 = as.z + ad.z; l3 = as.w + ad.w;
            l0 = l0 > 0.f ? l0 : 0.2f * l0;
            l1 = l1 > 0.f ? l1 : 0.2f * l1;
            l2 = l2 > 0.f ? l2 : 0.2f * l2;
            l3 = l3 > 0.f ? l3 : 0.2f * l3;
            degw = g_ewc[i];
        }
        mx0 = l0; mx1 = l1; mx2 = l2; mx3 = l3;
#pragma unroll
        for (int o = 16; o > 0; o >>= 1) {
            mx0 = fmaxf(mx0, __shfl_xor_sync(0xFFFFFFFFu, mx0, o));
            mx1 = fmaxf(mx1, __shfl_xor_sync(0xFFFFFFFFu, mx1, o));
            mx2 = fmaxf(mx2, __shfl_xor_sync(0xFFFFFFFFu, mx2, o));
            mx3 = fmaxf(mx3, __shfl_xor_sync(0xFFFFFFFFu, mx3, o));
            degw += __shfl_xor_sync(0xFFFFFFFFu, degw, o);
        }
        float e0 = act ? __expf(l0 - mx0) : 0.f;
        float e1 = act ? __expf(l1 - mx1) : 0.f;
        float e2 = act ? __expf(l2 - mx2) : 0.f;
        float e3 = act ? __expf(l3 - mx3) : 0.f;
        float s0 = e0, s1 = e1, s2 = e2, s3 = e3;
#pragma unroll
        for (int o = 16; o > 0; o >>= 1) {
            s0 += __shfl_xor_sync(0xFFFFFFFFu, s0, o);
            s1 += __shfl_xor_sync(0xFFFFFFFFu, s1, o);
            s2 += __shfl_xor_sync(0xFFFFFFFFu, s2, o);
            s3 += __shfl_xor_sync(0xFFFFFFFFu, s3, o);
        }
        if (act) {
            float4 al = make_float4(e0 / (s0 + 1e-16f), e1 / (s1 + 1e-16f),
                                    e2 / (s2 + 1e-16f), e3 / (s3 + 1e-16f));
            *(float4*)&g_alpha[(size_t)i * 4] = al;
        }
    } else {
        for (int i = beg + lane; i < end; i += 32) {
            int s = g_esrc[i];
            float4 as = *(const float4*)&g_asrc[s * 4];
            float l0 = as.x + ad.x, l1 = as.y + ad.y, l2 = as.z + ad.z, l3 = as.w + ad.w;
            l0 = l0 > 0.f ? l0 : 0.2f * l0;
            l1 = l1 > 0.f ? l1 : 0.2f * l1;
            l2 = l2 > 0.f ? l2 : 0.2f * l2;
            l3 = l3 > 0.f ? l3 : 0.2f * l3;
            *(float4*)&g_alpha[(size_t)i * 4] = make_float4(l0, l1, l2, l3);
            mx0 = fmaxf(mx0, l0); mx1 = fmaxf(mx1, l1);
            mx2 = fmaxf(mx2, l2); mx3 = fmaxf(mx3, l3);
            degw += g_ewc[i];
        }
#pragma unroll
        for (int o = 16; o > 0; o >>= 1) {
            mx0 = fmaxf(mx0, __shfl_xor_sync(0xFFFFFFFFu, mx0, o));
            mx1 = fmaxf(mx1, __shfl_xor_sync(0xFFFFFFFFu, mx1, o));
            mx2 = fmaxf(mx2, __shfl_xor_sync(0xFFFFFFFFu, mx2, o));
            mx3 = fmaxf(mx3, __shfl_xor_sync(0xFFFFFFFFu, mx3, o));
            degw += __shfl_xor_sync(0xFFFFFFFFu, degw, o);
        }
        float s0 = 0.f, s1 = 0.f, s2 = 0.f, s3 = 0.f;
        for (int i = beg + lane; i < end; i += 32) {
            float4 l = *(const float4*)&g_alpha[(size_t)i * 4];
            float e0 = __expf(l.x - mx0), e1 = __expf(l.y - mx1);
            float e2 = __expf(l.z - mx2), e3 = __expf(l.w - mx3);
            *(float4*)&g_alpha[(size_t)i * 4] = make_float4(e0, e1, e2, e3);
            s0 += e0; s1 += e1; s2 += e2; s3 += e3;
        }
#pragma unroll
        for (int o = 16; o > 0; o >>= 1) {
            s0 += __shfl_xor_sync(0xFFFFFFFFu, s0, o);
            s1 += __shfl_xor_sync(0xFFFFFFFFu, s1, o);
            s2 += __shfl_xor_sync(0xFFFFFFFFu, s2, o);
            s3 += __shfl_xor_sync(0xFFFFFFFFu, s3, o);
        }
        float r0 = 1.f / (s0 + 1e-16f), r1 = 1.f / (s1 + 1e-16f);
        float r2 = 1.f / (s2 + 1e-16f), r3 = 1.f / (s3 + 1e-16f);
        for (int i = beg + lane; i < end; i += 32) {
            float4 l = *(const float4*)&g_alpha[(size_t)i * 4];
            *(float4*)&g_alpha[(size_t)i * 4] = make_float4(l.x * r0, l.y * r1, l.z * r2, l.w * r3);
        }
    }
    if (lane == 0) g_dinv[d] = degw > 0.f ? rsqrtf(degw) : 0.0f;
}

// ---------------- GAT aggregation (per-node block, fp16 h, fp32 acc) ----------------
__global__ void __launch_bounds__(128)
k_aggregate(const float* __restrict__ b_gat) {
    int d = blockIdx.x;
    int tid = threadIdx.x;
    int head = tid >> 5;
    int c = tid * 4;
    float4 acc = *(const float4*)&b_gat[c];
    int beg = g_off[d], end = g_off[d + 1];
    int i = beg;
    for (; i + 1 < end; i += 2) {
        int s0 = g_esrc[i], s1 = g_esrc[i + 1];
        float a0 = g_alpha[(size_t)i * 4 + head];
        float a1 = g_alpha[(size_t)(i + 1) * 4 + head];
        const __half2* p0 = (const __half2*)&g_hh[(size_t)s0 * HC + c];
        const __half2* p1 = (const __half2*)&g_hh[(size_t)s1 * HC + c];
        float2 v0a = __half22float2(p0[0]), v0b = __half22float2(p0[1]);
        float2 v1a = __half22float2(p1[0]), v1b = __half22float2(p1[1]);
        acc.x = fmaf(v0a.x, a0, acc.x); acc.y = fmaf(v0a.y, a0, acc.y);
        acc.z = fmaf(v0b.x, a0, acc.z); acc.w = fmaf(v0b.y, a0, acc.w);
        acc.x = fmaf(v1a.x, a1, acc.x); acc.y = fmaf(v1a.y, a1, acc.y);
        acc.z = fmaf(v1b.x, a1, acc.z); acc.w = fmaf(v1b.y, a1, acc.w);
    }
    if (i < end) {
        int s0 = g_esrc[i];
        float a0 = g_alpha[(size_t)i * 4 + head];
        const __half2* p0 = (const __half2*)&g_hh[(size_t)s0 * HC + c];
        float2 v0a = __half22float2(p0[0]), v0b = __half22float2(p0[1]);
        acc.x = fmaf(v0a.x, a0, acc.x); acc.y = fmaf(v0a.y, a0, acc.y);
        acc.z = fmaf(v0b.x, a0, acc.z); acc.w = fmaf(v0b.y, a0, acc.w);
    }
    __half2* o = (__half2*)&g_out1h[(size_t)d * HC + c];
    o[0] = __floats2half2_rn(acc.x, acc.y);
    o[1] = __floats2half2_rn(acc.z, acc.w);
}

// ---------------- BN stats (fp16 in, fp32 accum) ----------------
__global__ void k_bnstats() {
    int col = threadIdx.x;
    float s = 0.f, s2 = 0.f;
    for (int r = blockIdx.x; r < N_NODES; r += gridDim.x) {
        float v = __half2float(g_out1h[(size_t)r * HC + col]);
        s += v; s2 += v * v;
    }
    atomicAdd(&g_colsum[col], s);
    atomicAdd(&g_colsum2[col], s2);
}

// ---------------- GCN gather (fp16 h2) ----------------
__global__ void k_gcn(const float* __restrict__ b_gcn, float* __restrict__ out) {
    int d    = (blockIdx.x * blockDim.x + threadIdx.x) >> 5;
    int lane = threadIdx.x & 31;
    if (d >= N_NODES) return;
    float dinv_d = g_dinv[d];
    float2 acc = *(const float2*)&b_gcn[lane * 2];
    int beg = g_off[d], end = g_off[d + 1];
    int i = beg;
    for (; i + 1 < end; i += 2) {
        int s0 = g_esrc[i], s1 = g_esrc[i + 1];
        float n0 = g_dinv[s0] * g_ewc[i] * dinv_d;
        float n1 = g_dinv[s1] * g_ewc[i + 1] * dinv_d;
        float2 v0 = __half22float2(*(const __half2*)&g_h2h[(size_t)s0 * HID + lane * 2]);
        float2 v1 = __half22float2(*(const __half2*)&g_h2h[(size_t)s1 * HID + lane * 2]);
        acc.x = fmaf(v0.x, n0, acc.x); acc.y = fmaf(v0.y, n0, acc.y);
        acc.x = fmaf(v1.x, n1, acc.x); acc.y = fmaf(v1.y, n1, acc.y);
    }
    if (i < end) {
        int s0 = g_esrc[i];
        float n0 = g_dinv[s0] * g_ewc[i] * dinv_d;
        float2 v0 = __half22float2(*(const __half2*)&g_h2h[(size_t)s0 * HID + lane * 2]);
        acc.x = fmaf(v0.x, n0, acc.x); acc.y = fmaf(v0.y, n0, acc.y);
    }
    *(float2*)&out[(size_t)d * HID + lane * 2] = acc;
}

// ---------------- launch ----------------
extern "C" void kernel_launch(void* const* d_in, const int* in_sizes, int n_in,
                              void* d_out, int out_size) {
    const float* x       = (const float*)d_in[0];
    const int*   ei      = (const int*)  d_in[1];
    const float* ew      = (const float*)d_in[2];
    const float* W_gat   = (const float*)d_in[3];
    const float* att_src = (const float*)d_in[4];
    const float* att_dst = (const float*)d_in[5];
    const float* b_gat   = (const float*)d_in[6];
    const float* gamma   = (const float*)d_in[7];
    const float* beta    = (const float*)d_in[8];
    const float* W_gcn   = (const float*)d_in[9];
    const float* b_gcn   = (const float*)d_in[10];
    float* out = (float*)d_out;

    int E  = in_sizes[1] / 2;
    int ET = E + N_NODES;

    static cudaStream_t s_side = nullptr;
    static cudaEvent_t ev_fork = nullptr, ev_join = nullptr;
    if (!s_side) {
        cudaFuncSetAttribute(k_gemm1, cudaFuncAttributeMaxDynamicSharedMemorySize, GEMM1_SMEM);
        cudaFuncSetAttribute(k_gemm2, cudaFuncAttributeMaxDynamicSharedMemorySize, GEMM2_SMEM);
        cudaStreamCreateWithFlags(&s_side, cudaStreamNonBlocking);
        cudaEventCreateWithFlags(&ev_fork, cudaEventDisableTiming);
        cudaEventCreateWithFlags(&ev_join, cudaEventDisableTiming);
    }

    // ---- fork: init + CSR build + W_gcn convert on side stream ----
    cudaEventRecord(ev_fork, 0);
    cudaStreamWaitEvent(s_side, ev_fork, 0);
    k_init<<<(N_NODES + 255) / 256, 256, 0, s_side>>>();
    k_count<<<(ET + 255) / 256, 256, 0, s_side>>>(ei, E);
    k_scan1<<<SCAN_BLOCKS, 256, 0, s_side>>>();
    k_scan2<<<1, 128, 0, s_side>>>();
    k_scan3<<<SCAN_BLOCKS, 256, 0, s_side>>>();
    k_fill<<<(ET + 255) / 256, 256, 0, s_side>>>(ei, ew, E);
    k_conv_wg<<<(HC * HID + 255) / 256, 256, 0, s_side>>>(W_gcn);
    cudaEventRecord(ev_join, s_side);

    // ---- main stream ----
    k_conv_a<<<((N_NODES * (F_IN / 4)) + 255) / 256, 256>>>(x);
    k_conv_bt<<<(F_IN * HC + 255) / 256, 256>>>(W_gat);

    dim3 g1(HC / BN, (N_NODES + BM - 1) / BM);   // (4, 235)
    k_gemm1<<<g1, 256, GEMM1_SMEM>>>(att_src, att_dst);

    cudaStreamWaitEvent(0, ev_join, 0);
    k_softmax<<<(N_NODES * 32 + 255) / 256, 256>>>();
    k_aggregate<<<N_NODES, 128>>>(b_gat);

    k_bnstats<<<240, 512>>>();
    k_conv_xr<<<(N_NODES + 63) / 64, 256>>>(gamma, beta);

    k_gemm2<<<(N_NODES + BM - 1) / BM, 256, GEMM2_SMEM>>>();
    k_gcn<<<(N_NODES * 32 + 255) / 256, 256>>>(b_gcn, out);
}